// round 8
// baseline (speedup 1.0000x reference)
#include <cuda_runtime.h>
#include <cuda_fp16.h>
#include <math.h>
#include <stdint.h>

#define B_ 2
#define S_ 2048
#define DM_ 2048
#define H_ 8
#define DH_ 128
#define INNER_ 1024
#define MROWS (B_*S_)   // 4096

// ---------------- scratch (device globals; no allocation allowed) ----------
__device__ float g_q[MROWS * INNER_];
__device__ float g_k[MROWS * INNER_];
__device__ float g_v[MROWS * INNER_];
__device__ float g_beta[MROWS * H_];
__device__ float g_amean[H_];

__device__ __align__(128) __half g_xhi[MROWS * DM_];
__device__ __align__(128) __half g_xlo[MROWS * DM_];
__device__ __align__(128) __half g_wqh[INNER_ * DM_];
__device__ __align__(128) __half g_wkh[INNER_ * DM_];
__device__ __align__(128) __half g_wvh[INNER_ * DM_];
__device__ __align__(128) __half g_woh[DM_ * INNER_];
__device__ __align__(128) __half g_ahi[MROWS * INNER_];
__device__ __align__(128) __half g_alo[MROWS * INNER_];

#define STWIN_ 128
#define STCH 4
#define STLEN (STWIN_/STCH)   // 32
__device__ float g_stpart[B_ * H_ * STCH * DH_ * DH_];

__device__ __forceinline__ float sigmoidf_(float x) {
    return 1.0f / (1.0f + expf(-x));
}

// ======================= PTX helpers ==============================
__device__ __forceinline__ uint32_t smem_u32(const void* p) {
    uint32_t a;
    asm("{ .reg .u64 t; cvta.to.shared.u64 t, %1; cvt.u32.u64 %0, t; }"
        : "=r"(a) : "l"(p));
    return a;
}

#define CP_ASYNC16(dst, src) \
    asm volatile("cp.async.cg.shared.global [%0], [%1], 16;" :: "r"(dst), "l"(src) : "memory")
#define CP_COMMIT() asm volatile("cp.async.commit_group;" ::: "memory")
#define CP_WAIT(n)  asm volatile("cp.async.wait_group %0;" :: "n"(n) : "memory")

__device__ __forceinline__ void ldsm_x4(uint32_t& r0, uint32_t& r1, uint32_t& r2, uint32_t& r3,
                                        uint32_t addr) {
    asm volatile("ldmatrix.sync.aligned.m8n8.x4.shared.b16 {%0,%1,%2,%3}, [%4];"
        : "=r"(r0), "=r"(r1), "=r"(r2), "=r"(r3) : "r"(addr));
}

__device__ __forceinline__ void mma16816(float* c, const uint32_t* a, uint32_t b0, uint32_t b1) {
    asm volatile(
        "mma.sync.aligned.m16n8k16.row.col.f32.f16.f16.f32 "
        "{%0,%1,%2,%3}, {%4,%5,%6,%7}, {%8,%9}, {%0,%1,%2,%3};"
        : "+f"(c[0]), "+f"(c[1]), "+f"(c[2]), "+f"(c[3])
        : "r"(a[0]), "r"(a[1]), "r"(a[2]), "r"(a[3]), "r"(b0), "r"(b1));
}

// ======================= conversions ==========================
__global__ void splitA_kernel(const float* __restrict__ src,
                              __half* __restrict__ hi,
                              __half* __restrict__ lo, int n4) {
    int i = blockIdx.x * blockDim.x + threadIdx.x;
    if (i >= n4) return;
    float4 v = ((const float4*)src)[i];
    __half h0 = __float2half(v.x);
    __half h1 = __float2half(v.y);
    __half h2 = __float2half(v.z);
    __half h3 = __float2half(v.w);
    __half l0 = __float2half(v.x - __half2float(h0));
    __half l1 = __float2half(v.y - __half2float(h1));
    __half l2 = __float2half(v.z - __half2float(h2));
    __half l3 = __float2half(v.w - __half2float(h3));
    __half2* hp = (__half2*)hi;
    __half2* lp = (__half2*)lo;
    hp[2*i]   = __half2(h0, h1);
    hp[2*i+1] = __half2(h2, h3);
    lp[2*i]   = __half2(l0, l1);
    lp[2*i+1] = __half2(l2, l3);
}

__global__ void cvt4_kernel(const float* __restrict__ s0, const float* __restrict__ s1,
                            const float* __restrict__ s2, const float* __restrict__ s3,
                            __half* __restrict__ d0, __half* __restrict__ d1,
                            __half* __restrict__ d2, __half* __restrict__ d3, int n4) {
    int i = blockIdx.x * blockDim.x + threadIdx.x;
    if (i >= n4) return;
    int seg = blockIdx.y;
    const float* s = (seg == 0) ? s0 : (seg == 1) ? s1 : (seg == 2) ? s2 : s3;
    __half* d = (seg == 0) ? d0 : (seg == 1) ? d1 : (seg == 2) ? d2 : d3;
    float4 v = ((const float4*)s)[i];
    __half2* p = (__half2*)d;
    p[2*i]   = __half2(__float2half(v.x), __float2half(v.y));
    p[2*i+1] = __half2(__float2half(v.z), __float2half(v.w));
}

// ======================= fp16 2-pass HMMA GEMM ==============================
#define NSTG 2
#define TILE_B 16384u
#define STG_BYTES (3u * TILE_B)
#define GEMM_SMEM (NSTG * STG_BYTES)  // 96KB

__global__ __launch_bounds__(256, 2) void hmma_gemm(
    const __half* __restrict__ Ah, const __half* __restrict__ Al,
    const __half* __restrict__ B0, const __half* __restrict__ B1,
    const __half* __restrict__ B2,
    float* __restrict__ C0, float* __restrict__ C1, float* __restrict__ C2,
    int K, int ldc) {
    extern __shared__ char smem[];
    uint32_t sm = smem_u32(smem);
    int tid = threadIdx.x;
    int lane = tid & 31;
    int wid = tid >> 5;
    int wm = wid & 1;
    int wn = wid >> 1;
    int m0 = blockIdx.y * 128;
    int n0 = blockIdx.x * 128;

    const __half* Bh;
    float* C;
    if (blockIdx.z == 0)      { Bh = B0; C = C0; }
    else if (blockIdx.z == 1) { Bh = B1; C = C1; }
    else                      { Bh = B2; C = C2; }

    int kiters = K >> 6;

    float acc[4][4][4];
    #pragma unroll
    for (int i = 0; i < 4; i++)
        #pragma unroll
        for (int j = 0; j < 4; j++)
            #pragma unroll
            for (int t = 0; t < 4; t++) acc[i][j][t] = 0.f;

    int lc = tid & 7;
    int lr = tid >> 3;

    #define ISSUE_STAGE(ip, buf) do {                                          \
        int _k0 = (ip) << 6;                                                   \
        const __half* _ah = Ah + (size_t)(m0 + lr) * K + _k0 + lc * 8;         \
        const __half* _al = Al + (size_t)(m0 + lr) * K + _k0 + lc * 8;         \
        const __half* _bh = Bh + (size_t)(n0 + lr) * K + _k0 + lc * 8;         \
        uint32_t _sb = sm + (buf) * STG_BYTES;                                 \
        _Pragma("unroll")                                                      \
        for (int _i = 0; _i < 4; _i++) {                                       \
            int _row = lr + 32 * _i;                                           \
            uint32_t _sw = ((uint32_t)_row << 7) + (((uint32_t)(lc ^ (_row & 7))) << 4); \
            size_t _go = (size_t)(32 * _i) * K;                                \
            CP_ASYNC16(_sb + _sw,              _ah + _go);                     \
            CP_ASYNC16(_sb + TILE_B + _sw,     _al + _go);                     \
            CP_ASYNC16(_sb + 2*TILE_B + _sw,   _bh + _go);                     \
        }                                                                      \
    } while (0)

    ISSUE_STAGE(0, 0); CP_COMMIT();

    for (int it = 0; it < kiters; ++it) {
        if (it + 1 < kiters) {
            ISSUE_STAGE(it + 1, (it + 1) & 1);
            CP_COMMIT();
            CP_WAIT(1);
        } else {
            CP_WAIT(0);
        }
        __syncthreads();

        uint32_t sah = sm + (it & 1) * STG_BYTES;
        uint32_t sal = sah + TILE_B;
        uint32_t sbh = sah + 2 * TILE_B;
        #pragma unroll
        for (int ks = 0; ks < 4; ++ks) {
            int ch = ks * 2 + (lane >> 4);
            uint32_t bfr[2][4];
            #pragma unroll
            for (int nt2 = 0; nt2 < 2; ++nt2) {
                int rowB = wn * 32 + nt2 * 16 + (lane & 7) + ((lane >> 3) & 1) * 8;
                uint32_t off = ((uint32_t)rowB << 7) + (((uint32_t)(ch ^ (rowB & 7))) << 4);
                ldsm_x4(bfr[nt2][0], bfr[nt2][1], bfr[nt2][2], bfr[nt2][3], sbh + off);
            }
            #pragma unroll
            for (int mt = 0; mt < 4; ++mt) {
                int rowA = wm * 64 + mt * 16 + (lane & 7) + ((lane >> 3) & 1) * 8;
                uint32_t off = ((uint32_t)rowA << 7) + (((uint32_t)(ch ^ (rowA & 7))) << 4);
                uint32_t ah[4], al[4];
                ldsm_x4(ah[0], ah[1], ah[2], ah[3], sah + off);
                ldsm_x4(al[0], al[1], al[2], al[3], sal + off);
                #pragma unroll
                for (int nt2 = 0; nt2 < 2; ++nt2) {
                    mma16816(acc[mt][nt2 * 2 + 0], ah, bfr[nt2][0], bfr[nt2][2]);
                    mma16816(acc[mt][nt2 * 2 + 1], ah, bfr[nt2][1], bfr[nt2][3]);
                    mma16816(acc[mt][nt2 * 2 + 0], al, bfr[nt2][0], bfr[nt2][2]);
                    mma16816(acc[mt][nt2 * 2 + 1], al, bfr[nt2][1], bfr[nt2][3]);
                }
            }
        }
        __syncthreads();
    }
    #undef ISSUE_STAGE

    #pragma unroll
    for (int mt = 0; mt < 4; ++mt) {
        int m = m0 + wm * 64 + mt * 16 + (lane >> 2);
        #pragma unroll
        for (int nt = 0; nt < 4; ++nt) {
            int n = n0 + wn * 32 + nt * 8 + (lane & 3) * 2;
            float* p = C + (size_t)m * ldc + n;
            *(float2*)p = make_float2(acc[mt][nt][0], acc[mt][nt][1]);
            *(float2*)(p + 8 * (size_t)ldc) = make_float2(acc[mt][nt][2], acc[mt][nt][3]);
        }
    }
}

// ---------------- alpha_mean per head ----------------
__global__ void amean_kernel(const float* __restrict__ alpha_log) {
    int w = threadIdx.x >> 5;
    int lane = threadIdx.x & 31;
    float s = 0.f;
    for (int d = lane; d < DH_; d += 32)
        s += sigmoidf_(alpha_log[w * DH_ + d]);
    #pragma unroll
    for (int o = 16; o; o >>= 1) s += __shfl_xor_sync(0xffffffffu, s, o);
    if (lane == 0) g_amean[w] = s / (float)DH_;
}

// ---------------- beta = sigmoid(x @ Wb^T + bb) ----------------
__global__ __launch_bounds__(256) void beta_kernel(const float* __restrict__ x,
                                                   const float* __restrict__ Wb,
                                                   const float* __restrict__ bb,
                                                   float* __restrict__ beta) {
    __shared__ float xs[DM_];
    int row = blockIdx.x;
    for (int i = threadIdx.x; i < DM_; i += 256)
        xs[i] = x[row * DM_ + i];
    __syncthreads();
    int w = threadIdx.x >> 5;
    int lane = threadIdx.x & 31;
    const float* wr = Wb + w * DM_;
    float sum = 0.f;
    for (int i = lane; i < DM_; i += 32)
        sum += xs[i] * wr[i];
    #pragma unroll
    for (int o = 16; o; o >>= 1) sum += __shfl_xor_sync(0xffffffffu, sum, o);
    if (lane == 0) beta[row * H_ + w] = sigmoidf_(sum + bb[w]);
}

// ---------------- RoPE in-place on q and k ----------------
__global__ void rope_kernel(float* __restrict__ q, float* __restrict__ k) {
    int idx = blockIdx.x * blockDim.x + threadIdx.x;
    int j = idx & 63;
    int h = (idx >> 6) & (H_ - 1);
    int row = idx >> 9;
    int s = row & (S_ - 1);
    float ex = (float)(2 * j) * (1.0f / (float)DH_);
    float inv = powf(10000.0f, -ex);
    float ang = (float)s * inv;
    float sn, c;
    sincosf(ang, &sn, &c);
    int base = row * INNER_ + h * DH_ + j;
    float x1 = q[base], x2 = q[base + 64];
    q[base]      = x1 * c - x2 * sn;
    q[base + 64] = x2 * c + x1 * sn;
    x1 = k[base]; x2 = k[base + 64];
    k[base]      = x1 * c - x2 * sn;
    k[base + 64] = x2 * c + x1 * sn;
}

// ---------------- smem-tiled windowed decay attention ----------------------
// Block: 8 warps = 8 consecutive s for one (b,h). Window union = 39 k/v rows
// staged in smem; inner loop reads smem only. Emits fp16 hi/lo.
#define WIN_ 32
#define ATT_S 8
#define ATT_ROWS (WIN_ - 1 + ATT_S)   // 39
__global__ __launch_bounds__(256) void attn_kernel(const float* __restrict__ q,
                                                   const float* __restrict__ k,
                                                   const float* __restrict__ v,
                                                   const float* __restrict__ beta,
                                                   __half* __restrict__ ahi,
                                                   __half* __restrict__ alo) {
    __shared__ float ks[ATT_ROWS * DH_];
    __shared__ float vs[ATT_ROWS * DH_];
    __shared__ float bs[ATT_ROWS];
    int tid = threadIdx.x;
    int wid = tid >> 5;
    int lane = tid & 31;
    int s0 = blockIdx.x * ATT_S;
    int h  = blockIdx.y;
    int b  = blockIdx.z;
    int base_t = s0 - (WIN_ - 1);     // may be negative

    size_t bh = (size_t)b * S_ * INNER_ + h * DH_;

    // stage k/v window + beta
    for (int i = tid; i < ATT_ROWS * 32; i += 256) {
        int r = i >> 5;
        int c = (i & 31) * 4;
        int t = base_t + r;
        float4 z = make_float4(0.f, 0.f, 0.f, 0.f);
        float4 kv = z, vv = z;
        if (t >= 0) {
            kv = *(const float4*)(k + bh + (size_t)t * INNER_ + c);
            vv = *(const float4*)(v + bh + (size_t)t * INNER_ + c);
        }
        *(float4*)&ks[r * DH_ + c] = kv;
        *(float4*)&vs[r * DH_ + c] = vv;
    }
    if (tid < ATT_ROWS) {
        int t = base_t + tid;
        bs[tid] = (t >= 0) ? beta[(size_t)(b * S_ + t) * H_ + h] : 0.f;
    }
    __syncthreads();

    int s = s0 + wid;
    float am = g_amean[h];
    float am2 = am * am;
    float am3 = am2 * am;
    float am4 = am2 * am2;
    const float4 qv = *(const float4*)(q + bh + (size_t)s * INNER_ + lane * 4);
    float4 acc = make_float4(0.f, 0.f, 0.f, 0.f);
    float decay = 1.f;
    int t_lo = s - (WIN_ - 1); if (t_lo < 0) t_lo = 0;
    int c4 = lane * 4;

    for (int t4 = s; t4 >= t_lo; t4 -= 4) {
        int r0 = t4 - base_t;
        bool m1 = t4 - 1 >= t_lo, m2 = t4 - 2 >= t_lo, m3 = t4 - 3 >= t_lo;
        float4 z = make_float4(0.f, 0.f, 0.f, 0.f);
        float4 k0 = *(const float4*)&ks[r0 * DH_ + c4];
        float4 v0 = *(const float4*)&vs[r0 * DH_ + c4];
        float4 k1 = m1 ? *(const float4*)&ks[(r0-1) * DH_ + c4] : z;
        float4 v1 = m1 ? *(const float4*)&vs[(r0-1) * DH_ + c4] : z;
        float4 k2 = m2 ? *(const float4*)&ks[(r0-2) * DH_ + c4] : z;
        float4 v2 = m2 ? *(const float4*)&vs[(r0-2) * DH_ + c4] : z;
        float4 k3 = m3 ? *(const float4*)&ks[(r0-3) * DH_ + c4] : z;
        float4 v3 = m3 ? *(const float4*)&vs[(r0-3) * DH_ + c4] : z;
        float d0 = qv.x*k0.x + qv.y*k0.y + qv.z*k0.z + qv.w*k0.w;
        float d1 = qv.x*k1.x + qv.y*k1.y + qv.z*k1.z + qv.w*k1.w;
        float d2 = qv.x*k2.x + qv.y*k2.y + qv.z*k2.z + qv.w*k2.w;
        float d3 = qv.x*k3.x + qv.y*k3.y + qv.z*k3.z + qv.w*k3.w;
        #pragma unroll
        for (int o = 16; o; o >>= 1) {
            d0 += __shfl_xor_sync(0xffffffffu, d0, o);
            d1 += __shfl_xor_sync(0xffffffffu, d1, o);
            d2 += __shfl_xor_sync(0xffffffffu, d2, o);
            d3 += __shfl_xor_sync(0xffffffffu, d3, o);
        }
        float w0 = d0 * decay * bs[r0];
        float w1 = m1 ? d1 * decay * am  * bs[r0-1] : 0.f;
        float w2 = m2 ? d2 * decay * am2 * bs[r0-2] : 0.f;
        float w3 = m3 ? d3 * decay * am3 * bs[r0-3] : 0.f;
        acc.x = fmaf(w0, v0.x, fmaf(w1, v1.x, fmaf(w2, v2.x, fmaf(w3, v3.x, acc.x))));
        acc.y = fmaf(w0, v0.y, fmaf(w1, v1.y, fmaf(w2, v2.y, fmaf(w3, v3.y, acc.y))));
        acc.z = fmaf(w0, v0.z, fmaf(w1, v1.z, fmaf(w2, v2.z, fmaf(w3, v3.z, acc.z))));
        acc.w = fmaf(w0, v0.w, fmaf(w1, v1.w, fmaf(w2, v2.w, fmaf(w3, v3.w, acc.w))));
        decay *= am4;
    }
    size_t o = bh + (size_t)s * INNER_ + c4;
    __half h0 = __float2half(acc.x);
    __half h1 = __float2half(acc.y);
    __half h2 = __float2half(acc.z);
    __half h3 = __float2half(acc.w);
    ((__half2*)(ahi + o))[0] = __half2(h0, h1);
    ((__half2*)(ahi + o))[1] = __half2(h2, h3);
    ((__half2*)(alo + o))[0] = __half2(__float2half(acc.x - __half2float(h0)),
                                       __float2half(acc.y - __half2float(h1)));
    ((__half2*)(alo + o))[1] = __half2(__float2half(acc.z - __half2float(h2)),
                                       __float2half(acc.w - __half2float(h3)));
}

// ---------------- recurrent state: partial chunks + combine ----------------
__global__ __launch_bounds__(256) void state_part(const float* __restrict__ k,
                                                  const float* __restrict__ v,
                                                  const float* __restrict__ beta,
                                                  const float* __restrict__ alpha_log,
                                                  float* __restrict__ part) {
    int bh = blockIdx.x >> 2;
    int c  = blockIdx.x & 3;
    int b = bh >> 3;
    int h = bh & 7;
    int tid = threadIdx.x;
    int d = tid >> 1;
    int e0 = (tid & 1) * 64;
    __shared__ float ks[DH_], vs[DH_];
    float st[64];
    #pragma unroll
    for (int e = 0; e < 64; e++) st[e] = 0.f;
    float ad = sigmoidf_(alpha_log[h * DH_ + d]);
    int tbeg = S_ - STWIN_ + c * STLEN;
    for (int t = tbeg; t < tbeg + STLEN; t++) {
        __syncthreads();
        size_t base = (size_t)(b * S_ + t) * INNER_ + h * DH_;
        if (tid < 128) ks[tid] = k[base + tid];
        else           vs[tid - 128] = v[base + tid - 128];
        __syncthreads();
        float kb = ks[d] * beta[(b * S_ + t) * H_ + h];
        #pragma unroll
        for (int e = 0; e < 64; e++)
            st[e] = fmaf(ad, st[e], kb * vs[e0 + e]);
    }
    float* op = part + (((size_t)bh * STCH + c) * DH_ + d) * DH_ + e0;
    #pragma unroll
    for (int e = 0; e < 64; e++) op[e] = st[e];
}

__global__ __launch_bounds__(256) void state_comb(const float* __restrict__ part,
                                                  const float* __restrict__ alpha_log,
                                                  float* __restrict__ stout) {
    int bh = blockIdx.x;
    int h = bh & 7;
    int tid = threadIdx.x;
    int d = tid >> 1;
    int e0 = (tid & 1) * 64;
    float ad = sigmoidf_(alpha_log[h * DH_ + d]);
    float a32 = ad;
    a32 *= a32; a32 *= a32; a32 *= a32; a32 *= a32; a32 *= a32;
    const float* p0 = part + (((size_t)bh * STCH + 0) * DH_ + d) * DH_ + e0;
    const float* p1 = part + (((size_t)bh * STCH + 1) * DH_ + d) * DH_ + e0;
    const float* p2 = part + (((size_t)bh * STCH + 2) * DH_ + d) * DH_ + e0;
    const float* p3 = part + (((size_t)bh * STCH + 3) * DH_ + d) * DH_ + e0;
    float* op = stout + ((size_t)bh * DH_ + d) * DH_ + e0;
    #pragma unroll
    for (int e = 0; e < 64; e++) {
        float r = p0[e];
        r = fmaf(r, a32, p1[e]);
        r = fmaf(r, a32, p2[e]);
        r = fmaf(r, a32, p3[e]);
        op[e] = r;
    }
}

// ---------------- launch ----------------
extern "C" void kernel_launch(void* const* d_in, const int* in_sizes, int n_in,
                              void* d_out, int out_size) {
    const float* x         = (const float*)d_in[0];
    const float* Wq        = (const float*)d_in[1];
    const float* Wk        = (const float*)d_in[2];
    const float* Wv        = (const float*)d_in[3];
    const float* Wo        = (const float*)d_in[4];
    const float* Wb        = (const float*)d_in[5];
    const float* bb        = (const float*)d_in[6];
    const float* alpha_log = (const float*)d_in[7];
    float* out = (float*)d_out;

    float *q, *k, *v, *beta, *stpart;
    cudaGetSymbolAddress((void**)&q,      g_q);
    cudaGetSymbolAddress((void**)&k,      g_k);
    cudaGetSymbolAddress((void**)&v,      g_v);
    cudaGetSymbolAddress((void**)&beta,   g_beta);
    cudaGetSymbolAddress((void**)&stpart, g_stpart);
    __half *xhi, *xlo, *wqh, *wkh, *wvh, *woh, *ahi, *alo;
    cudaGetSymbolAddress((void**)&xhi, g_xhi);
    cudaGetSymbolAddress((void**)&xlo, g_xlo);
    cudaGetSymbolAddress((void**)&wqh, g_wqh);
    cudaGetSymbolAddress((void**)&wkh, g_wkh);
    cudaGetSymbolAddress((void**)&wvh, g_wvh);
    cudaGetSymbolAddress((void**)&woh, g_woh);
    cudaGetSymbolAddress((void**)&ahi, g_ahi);
    cudaGetSymbolAddress((void**)&alo, g_alo);

    cudaFuncSetAttribute(hmma_gemm, cudaFuncAttributeMaxDynamicSharedMemorySize, GEMM_SMEM);

    amean_kernel<<<1, 256>>>(alpha_log);
    beta_kernel<<<MROWS, 256>>>(x, Wb, bb, beta);

    splitA_kernel<<<(MROWS*DM_/4 + 255)/256, 256>>>(x, xhi, xlo, MROWS*DM_/4);
    dim3 gcvt((INNER_*DM_/4 + 255)/256, 4);
    cvt4_kernel<<<gcvt, 256>>>(Wq, Wk, Wv, Wo, wqh, wkh, wvh, woh, INNER_*DM_/4);

    dim3 gqkv(INNER_/128, MROWS/128, 3);
    hmma_gemm<<<gqkv, 256, GEMM_SMEM>>>(xhi, xlo,
                                        wqh, wkh, wvh,
                                        q, k, v, DM_, INNER_);

    rope_kernel<<<(B_ * S_ * H_ * 64) / 256, 256>>>(q, k);

    dim3 gattn(S_/ATT_S, H_, B_);
    attn_kernel<<<gattn, 256>>>(q, k, v, beta, ahi, alo);

    dim3 gout(DM_/128, MROWS/128, 1);
    hmma_gemm<<<gout, 256, GEMM_SMEM>>>(ahi, alo,
                                        woh, woh, woh,
                                        out, out, out, INNER_, DM_);

    state_part<<<B_ * H_ * STCH, 256>>>(k, v, beta, alpha_log, stpart);
    state_comb<<<B_ * H_, 256>>>(stpart, alpha_log, out + (size_t)MROWS * DM_);
}

// round 9
// speedup vs baseline: 1.3972x; 1.3972x over previous
#include <cuda_runtime.h>
#include <cuda_fp16.h>
#include <math.h>
#include <stdint.h>

#define B_ 2
#define S_ 2048
#define DM_ 2048
#define H_ 8
#define DH_ 128
#define INNER_ 1024
#define MROWS (B_*S_)   // 4096

// ---------------- scratch (device globals; no allocation allowed) ----------
__device__ float g_q[MROWS * INNER_];
__device__ float g_k[MROWS * INNER_];
__device__ float g_v[MROWS * INNER_];
__device__ float g_beta[MROWS * H_];
__device__ float g_amean[H_];

__device__ __align__(128) __half g_xh[MROWS * DM_];
__device__ __align__(128) __half g_wqh[INNER_ * DM_];
__device__ __align__(128) __half g_wkh[INNER_ * DM_];
__device__ __align__(128) __half g_wvh[INNER_ * DM_];
__device__ __align__(128) __half g_woh[DM_ * INNER_];
__device__ __align__(128) __half g_ah[MROWS * INNER_];

#define STWIN_ 128
#define STCH 4
#define STLEN (STWIN_/STCH)   // 32
__device__ float g_stpart[B_ * H_ * STCH * DH_ * DH_];

__device__ __forceinline__ float sigmoidf_(float x) {
    return 1.0f / (1.0f + expf(-x));
}

// ======================= PTX helpers ==============================
__device__ __forceinline__ uint32_t smem_u32(const void* p) {
    uint32_t a;
    asm("{ .reg .u64 t; cvta.to.shared.u64 t, %1; cvt.u32.u64 %0, t; }"
        : "=r"(a) : "l"(p));
    return a;
}

#define CP_ASYNC16(dst, src) \
    asm volatile("cp.async.cg.shared.global [%0], [%1], 16;" :: "r"(dst), "l"(src) : "memory")
#define CP_COMMIT() asm volatile("cp.async.commit_group;" ::: "memory")
#define CP_WAIT(n)  asm volatile("cp.async.wait_group %0;" :: "n"(n) : "memory")

__device__ __forceinline__ void ldsm_x4(uint32_t& r0, uint32_t& r1, uint32_t& r2, uint32_t& r3,
                                        uint32_t addr) {
    asm volatile("ldmatrix.sync.aligned.m8n8.x4.shared.b16 {%0,%1,%2,%3}, [%4];"
        : "=r"(r0), "=r"(r1), "=r"(r2), "=r"(r3) : "r"(addr));
}

__device__ __forceinline__ void mma16816(float* c, const uint32_t* a, uint32_t b0, uint32_t b1) {
    asm volatile(
        "mma.sync.aligned.m16n8k16.row.col.f32.f16.f16.f32 "
        "{%0,%1,%2,%3}, {%4,%5,%6,%7}, {%8,%9}, {%0,%1,%2,%3};"
        : "+f"(c[0]), "+f"(c[1]), "+f"(c[2]), "+f"(c[3])
        : "r"(a[0]), "r"(a[1]), "r"(a[2]), "r"(a[3]), "r"(b0), "r"(b1));
}

// ======================= conversions ==========================
__global__ void cvt1_kernel(const float* __restrict__ src,
                            __half* __restrict__ dst, int n4) {
    int i = blockIdx.x * blockDim.x + threadIdx.x;
    if (i >= n4) return;
    float4 v = ((const float4*)src)[i];
    __half2* p = (__half2*)dst;
    p[2*i]   = __half2(__float2half(v.x), __float2half(v.y));
    p[2*i+1] = __half2(__float2half(v.z), __float2half(v.w));
}

__global__ void cvt4_kernel(const float* __restrict__ s0, const float* __restrict__ s1,
                            const float* __restrict__ s2, const float* __restrict__ s3,
                            __half* __restrict__ d0, __half* __restrict__ d1,
                            __half* __restrict__ d2, __half* __restrict__ d3, int n4) {
    int i = blockIdx.x * blockDim.x + threadIdx.x;
    if (i >= n4) return;
    int seg = blockIdx.y;
    const float* s = (seg == 0) ? s0 : (seg == 1) ? s1 : (seg == 2) ? s2 : s3;
    __half* d = (seg == 0) ? d0 : (seg == 1) ? d1 : (seg == 2) ? d2 : d3;
    float4 v = ((const float4*)s)[i];
    __half2* p = (__half2*)d;
    p[2*i]   = __half2(__float2half(v.x), __float2half(v.y));
    p[2*i+1] = __half2(__float2half(v.z), __float2half(v.w));
}

// ======================= fp16 1-pass HMMA GEMM ==============================
// C[M,N](fp32) = Ah[M,K] @ Bh[N,K]^T (both single-rounded fp16, fp32 accum)
// 128x128 CTA tile, k-chunk 64 halves (128B), 3-stage cp.async, 2 CTAs/SM.
#define NSTG 3
#define TILE_B 16384u                 // one operand tile: 128 rows x 128B
#define STG_BYTES (2u * TILE_B)       // Ah | Bh = 32KB
#define GEMM_SMEM (NSTG * STG_BYTES)  // 96KB

__global__ __launch_bounds__(256, 2) void hmma_gemm(
    const __half* __restrict__ Ah,
    const __half* __restrict__ B0, const __half* __restrict__ B1,
    const __half* __restrict__ B2,
    float* __restrict__ C0, float* __restrict__ C1, float* __restrict__ C2,
    int K, int ldc) {
    extern __shared__ char smem[];
    uint32_t sm = smem_u32(smem);
    int tid = threadIdx.x;
    int lane = tid & 31;
    int wid = tid >> 5;
    int wm = wid & 1;          // 2 M-blocks of 64
    int wn = wid >> 1;         // 4 N-blocks of 32
    int m0 = blockIdx.y * 128;
    int n0 = blockIdx.x * 128;

    const __half* Bh;
    float* C;
    if (blockIdx.z == 0)      { Bh = B0; C = C0; }
    else if (blockIdx.z == 1) { Bh = B1; C = C1; }
    else                      { Bh = B2; C = C2; }

    int kiters = K >> 6;

    float acc[4][4][4];
    #pragma unroll
    for (int i = 0; i < 4; i++)
        #pragma unroll
        for (int j = 0; j < 4; j++)
            #pragma unroll
            for (int t = 0; t < 4; t++) acc[i][j][t] = 0.f;

    int lc = tid & 7;          // 16B chunk col within 128B row
    int lr = tid >> 3;         // 0..31

    #define ISSUE_STAGE(ip, buf) do {                                          \
        int _k0 = (ip) << 6;                                                   \
        const __half* _ah = Ah + (size_t)(m0 + lr) * K + _k0 + lc * 8;         \
        const __half* _bh = Bh + (size_t)(n0 + lr) * K + _k0 + lc * 8;         \
        uint32_t _sb = sm + (buf) * STG_BYTES;                                 \
        _Pragma("unroll")                                                      \
        for (int _i = 0; _i < 4; _i++) {                                       \
            int _row = lr + 32 * _i;                                           \
            uint32_t _sw = ((uint32_t)_row << 7) + (((uint32_t)(lc ^ (_row & 7))) << 4); \
            size_t _go = (size_t)(32 * _i) * K;                                \
            CP_ASYNC16(_sb + _sw,          _ah + _go);                         \
            CP_ASYNC16(_sb + TILE_B + _sw, _bh + _go);                         \
        }                                                                      \
    } while (0)

    ISSUE_STAGE(0, 0); CP_COMMIT();
    if (kiters > 1) ISSUE_STAGE(1, 1);
    CP_COMMIT();

    int buf = 0;
    int ibuf = 2;
    for (int it = 0; it < kiters; ++it) {
        if (it + 2 < kiters) ISSUE_STAGE(it + 2, ibuf);
        CP_COMMIT();
        CP_WAIT(2);
        __syncthreads();

        uint32_t sah = sm + buf * STG_BYTES;
        uint32_t sbh = sah + TILE_B;
        #pragma unroll
        for (int ks = 0; ks < 4; ++ks) {
            int ch = ks * 2 + (lane >> 4);
            uint32_t bfr[2][4];
            #pragma unroll
            for (int nt2 = 0; nt2 < 2; ++nt2) {
                int rowB = wn * 32 + nt2 * 16 + (lane & 7) + ((lane >> 3) & 1) * 8;
                uint32_t off = ((uint32_t)rowB << 7) + (((uint32_t)(ch ^ (rowB & 7))) << 4);
                ldsm_x4(bfr[nt2][0], bfr[nt2][1], bfr[nt2][2], bfr[nt2][3], sbh + off);
            }
            #pragma unroll
            for (int mt = 0; mt < 4; ++mt) {
                int rowA = wm * 64 + mt * 16 + (lane & 7) + ((lane >> 3) & 1) * 8;
                uint32_t off = ((uint32_t)rowA << 7) + (((uint32_t)(ch ^ (rowA & 7))) << 4);
                uint32_t a[4];
                ldsm_x4(a[0], a[1], a[2], a[3], sah + off);
                #pragma unroll
                for (int nt2 = 0; nt2 < 2; ++nt2) {
                    mma16816(acc[mt][nt2 * 2 + 0], a, bfr[nt2][0], bfr[nt2][2]);
                    mma16816(acc[mt][nt2 * 2 + 1], a, bfr[nt2][1], bfr[nt2][3]);
                }
            }
        }
        __syncthreads();
        buf = (buf == 2) ? 0 : buf + 1;
        ibuf = (ibuf == 2) ? 0 : ibuf + 1;
    }
    #undef ISSUE_STAGE

    // -------- epilogue --------
    #pragma unroll
    for (int mt = 0; mt < 4; ++mt) {
        int m = m0 + wm * 64 + mt * 16 + (lane >> 2);
        #pragma unroll
        for (int nt = 0; nt < 4; ++nt) {
            int n = n0 + wn * 32 + nt * 8 + (lane & 3) * 2;
            float* p = C + (size_t)m * ldc + n;
            *(float2*)p = make_float2(acc[mt][nt][0], acc[mt][nt][1]);
            *(float2*)(p + 8 * (size_t)ldc) = make_float2(acc[mt][nt][2], acc[mt][nt][3]);
        }
    }
}

// ---------------- alpha_mean per head ----------------
__global__ void amean_kernel(const float* __restrict__ alpha_log) {
    int w = threadIdx.x >> 5;
    int lane = threadIdx.x & 31;
    float s = 0.f;
    for (int d = lane; d < DH_; d += 32)
        s += sigmoidf_(alpha_log[w * DH_ + d]);
    #pragma unroll
    for (int o = 16; o; o >>= 1) s += __shfl_xor_sync(0xffffffffu, s, o);
    if (lane == 0) g_amean[w] = s / (float)DH_;
}

// ---------------- beta = sigmoid(x @ Wb^T + bb) ----------------
__global__ __launch_bounds__(256) void beta_kernel(const float* __restrict__ x,
                                                   const float* __restrict__ Wb,
                                                   const float* __restrict__ bb,
                                                   float* __restrict__ beta) {
    __shared__ float xs[DM_];
    int row = blockIdx.x;
    for (int i = threadIdx.x; i < DM_; i += 256)
        xs[i] = x[row * DM_ + i];
    __syncthreads();
    int w = threadIdx.x >> 5;
    int lane = threadIdx.x & 31;
    const float* wr = Wb + w * DM_;
    float sum = 0.f;
    for (int i = lane; i < DM_; i += 32)
        sum += xs[i] * wr[i];
    #pragma unroll
    for (int o = 16; o; o >>= 1) sum += __shfl_xor_sync(0xffffffffu, sum, o);
    if (lane == 0) beta[row * H_ + w] = sigmoidf_(sum + bb[w]);
}

// ---------------- RoPE in-place on q and k ----------------
__global__ void rope_kernel(float* __restrict__ q, float* __restrict__ k) {
    int idx = blockIdx.x * blockDim.x + threadIdx.x;
    int j = idx & 63;
    int h = (idx >> 6) & (H_ - 1);
    int row = idx >> 9;
    int s = row & (S_ - 1);
    float ex = (float)(2 * j) * (1.0f / (float)DH_);
    float inv = powf(10000.0f, -ex);
    float ang = (float)s * inv;
    float sn, c;
    sincosf(ang, &sn, &c);
    int base = row * INNER_ + h * DH_ + j;
    float x1 = q[base], x2 = q[base + 64];
    q[base]      = x1 * c - x2 * sn;
    q[base + 64] = x2 * c + x1 * sn;
    x1 = k[base]; x2 = k[base + 64];
    k[base]      = x1 * c - x2 * sn;
    k[base + 64] = x2 * c + x1 * sn;
}

// ---------------- windowed decay attention (4-way ILP, emits fp16) ---------
#define WIN_ 32
__global__ __launch_bounds__(256) void attn_kernel(const float* __restrict__ q,
                                                   const float* __restrict__ k,
                                                   const float* __restrict__ v,
                                                   const float* __restrict__ beta,
                                                   __half* __restrict__ ah) {
    int gw = (blockIdx.x * 256 + threadIdx.x) >> 5;
    int lane = threadIdx.x & 31;
    int s = gw & (S_ - 1);
    int h = (gw >> 11) & (H_ - 1);
    int b = gw >> 14;
    float am = g_amean[h];
    float am2 = am * am;
    float am3 = am2 * am;
    float am4 = am2 * am2;
    size_t colbase = (size_t)b * S_ * INNER_ + h * DH_ + lane * 4;
    const float4 qv = *(const float4*)(q + colbase + (size_t)s * INNER_);
    float4 acc = make_float4(0.f, 0.f, 0.f, 0.f);
    float decay = 1.f;
    int t_lo = s - (WIN_ - 1); if (t_lo < 0) t_lo = 0;
    const float* betab = beta + (size_t)b * S_ * H_ + h;

    for (int t4 = s; t4 >= t_lo; t4 -= 4) {
        int t1 = t4 - 1, t2 = t4 - 2, t3 = t4 - 3;
        bool m1 = t1 >= t_lo, m2 = t2 >= t_lo, m3 = t3 >= t_lo;
        float4 z = make_float4(0.f, 0.f, 0.f, 0.f);
        float4 k0 = *(const float4*)(k + colbase + (size_t)t4 * INNER_);
        float4 v0 = *(const float4*)(v + colbase + (size_t)t4 * INNER_);
        float4 k1 = m1 ? *(const float4*)(k + colbase + (size_t)t1 * INNER_) : z;
        float4 v1 = m1 ? *(const float4*)(v + colbase + (size_t)t1 * INNER_) : z;
        float4 k2 = m2 ? *(const float4*)(k + colbase + (size_t)t2 * INNER_) : z;
        float4 v2 = m2 ? *(const float4*)(v + colbase + (size_t)t2 * INNER_) : z;
        float4 k3 = m3 ? *(const float4*)(k + colbase + (size_t)t3 * INNER_) : z;
        float4 v3 = m3 ? *(const float4*)(v + colbase + (size_t)t3 * INNER_) : z;
        float d0 = qv.x*k0.x + qv.y*k0.y + qv.z*k0.z + qv.w*k0.w;
        float d1 = qv.x*k1.x + qv.y*k1.y + qv.z*k1.z + qv.w*k1.w;
        float d2 = qv.x*k2.x + qv.y*k2.y + qv.z*k2.z + qv.w*k2.w;
        float d3 = qv.x*k3.x + qv.y*k3.y + qv.z*k3.z + qv.w*k3.w;
        #pragma unroll
        for (int o = 16; o; o >>= 1) {
            d0 += __shfl_xor_sync(0xffffffffu, d0, o);
            d1 += __shfl_xor_sync(0xffffffffu, d1, o);
            d2 += __shfl_xor_sync(0xffffffffu, d2, o);
            d3 += __shfl_xor_sync(0xffffffffu, d3, o);
        }
        float bt0 = betab[(size_t)t4 * H_];
        float bt1 = m1 ? betab[(size_t)t1 * H_] : 0.f;
        float bt2 = m2 ? betab[(size_t)t2 * H_] : 0.f;
        float bt3 = m3 ? betab[(size_t)t3 * H_] : 0.f;
        float w0 = d0 * decay * bt0;
        float w1 = d1 * decay * am  * bt1;
        float w2 = d2 * decay * am2 * bt2;
        float w3 = d3 * decay * am3 * bt3;
        acc.x = fmaf(w0, v0.x, fmaf(w1, v1.x, fmaf(w2, v2.x, fmaf(w3, v3.x, acc.x))));
        acc.y = fmaf(w0, v0.y, fmaf(w1, v1.y, fmaf(w2, v2.y, fmaf(w3, v3.y, acc.y))));
        acc.z = fmaf(w0, v0.z, fmaf(w1, v1.z, fmaf(w2, v2.z, fmaf(w3, v3.z, acc.z))));
        acc.w = fmaf(w0, v0.w, fmaf(w1, v1.w, fmaf(w2, v2.w, fmaf(w3, v3.w, acc.w))));
        decay *= am4;
    }
    size_t o = colbase + (size_t)s * INNER_;
    ((__half2*)(ah + o))[0] = __half2(__float2half(acc.x), __float2half(acc.y));
    ((__half2*)(ah + o))[1] = __half2(__float2half(acc.z), __float2half(acc.w));
}

// ---------------- recurrent state: partial chunks + combine ----------------
__global__ __launch_bounds__(256) void state_part(const float* __restrict__ k,
                                                  const float* __restrict__ v,
                                                  const float* __restrict__ beta,
                                                  const float* __restrict__ alpha_log,
                                                  float* __restrict__ part) {
    int bh = blockIdx.x >> 2;
    int c  = blockIdx.x & 3;
    int b = bh >> 3;
    int h = bh & 7;
    int tid = threadIdx.x;
    int d = tid >> 1;
    int e0 = (tid & 1) * 64;
    __shared__ float ks[DH_], vs[DH_];
    float st[64];
    #pragma unroll
    for (int e = 0; e < 64; e++) st[e] = 0.f;
    float ad = sigmoidf_(alpha_log[h * DH_ + d]);
    int tbeg = S_ - STWIN_ + c * STLEN;
    for (int t = tbeg; t < tbeg + STLEN; t++) {
        __syncthreads();
        size_t base = (size_t)(b * S_ + t) * INNER_ + h * DH_;
        if (tid < 128) ks[tid] = k[base + tid];
        else           vs[tid - 128] = v[base + tid - 128];
        __syncthreads();
        float kb = ks[d] * beta[(b * S_ + t) * H_ + h];
        #pragma unroll
        for (int e = 0; e < 64; e++)
            st[e] = fmaf(ad, st[e], kb * vs[e0 + e]);
    }
    float* op = part + (((size_t)bh * STCH + c) * DH_ + d) * DH_ + e0;
    #pragma unroll
    for (int e = 0; e < 64; e++) op[e] = st[e];
}

__global__ __launch_bounds__(256) void state_comb(const float* __restrict__ part,
                                                  const float* __restrict__ alpha_log,
                                                  float* __restrict__ stout) {
    int bh = blockIdx.x;
    int h = bh & 7;
    int tid = threadIdx.x;
    int d = tid >> 1;
    int e0 = (tid & 1) * 64;
    float ad = sigmoidf_(alpha_log[h * DH_ + d]);
    float a32 = ad;
    a32 *= a32; a32 *= a32; a32 *= a32; a32 *= a32; a32 *= a32;
    const float* p0 = part + (((size_t)bh * STCH + 0) * DH_ + d) * DH_ + e0;
    const float* p1 = part + (((size_t)bh * STCH + 1) * DH_ + d) * DH_ + e0;
    const float* p2 = part + (((size_t)bh * STCH + 2) * DH_ + d) * DH_ + e0;
    const float* p3 = part + (((size_t)bh * STCH + 3) * DH_ + d) * DH_ + e0;
    float* op = stout + ((size_t)bh * DH_ + d) * DH_ + e0;
    #pragma unroll
    for (int e = 0; e < 64; e++) {
        float r = p0[e];
        r = fmaf(r, a32, p1[e]);
        r = fmaf(r, a32, p2[e]);
        r = fmaf(r, a32, p3[e]);
        op[e] = r;
    }
}

// ---------------- launch ----------------
extern "C" void kernel_launch(void* const* d_in, const int* in_sizes, int n_in,
                              void* d_out, int out_size) {
    const float* x         = (const float*)d_in[0];
    const float* Wq        = (const float*)d_in[1];
    const float* Wk        = (const float*)d_in[2];
    const float* Wv        = (const float*)d_in[3];
    const float* Wo        = (const float*)d_in[4];
    const float* Wb        = (const float*)d_in[5];
    const float* bb        = (const float*)d_in[6];
    const float* alpha_log = (const float*)d_in[7];
    float* out = (float*)d_out;

    float *q, *k, *v, *beta, *stpart;
    cudaGetSymbolAddress((void**)&q,      g_q);
    cudaGetSymbolAddress((void**)&k,      g_k);
    cudaGetSymbolAddress((void**)&v,      g_v);
    cudaGetSymbolAddress((void**)&beta,   g_beta);
    cudaGetSymbolAddress((void**)&stpart, g_stpart);
    __half *xh, *wqh, *wkh, *wvh, *woh, *ah;
    cudaGetSymbolAddress((void**)&xh,  g_xh);
    cudaGetSymbolAddress((void**)&wqh, g_wqh);
    cudaGetSymbolAddress((void**)&wkh, g_wkh);
    cudaGetSymbolAddress((void**)&wvh, g_wvh);
    cudaGetSymbolAddress((void**)&woh, g_woh);
    cudaGetSymbolAddress((void**)&ah,  g_ah);

    cudaFuncSetAttribute(hmma_gemm, cudaFuncAttributeMaxDynamicSharedMemorySize, GEMM_SMEM);

    amean_kernel<<<1, 256>>>(alpha_log);
    beta_kernel<<<MROWS, 256>>>(x, Wb, bb, beta);

    cvt1_kernel<<<(MROWS*DM_/4 + 255)/256, 256>>>(x, xh, MROWS*DM_/4);
    dim3 gcvt((INNER_*DM_/4 + 255)/256, 4);
    cvt4_kernel<<<gcvt, 256>>>(Wq, Wk, Wv, Wo, wqh, wkh, wvh, woh, INNER_*DM_/4);

    // QKV: fused 3-way GEMM, M=4096, N=1024, K=2048
    dim3 gqkv(INNER_/128, MROWS/128, 3);
    hmma_gemm<<<gqkv, 256, GEMM_SMEM>>>(xh, wqh, wkh, wvh,
                                        q, k, v, DM_, INNER_);

    rope_kernel<<<(B_ * S_ * H_ * 64) / 256, 256>>>(q, k);
    attn_kernel<<<(B_ * H_ * S_) / 8, 256>>>(q, k, v, beta, ah);

    // O-proj: M=4096, N=2048, K=1024
    dim3 gout(DM_/128, MROWS/128, 1);
    hmma_gemm<<<gout, 256, GEMM_SMEM>>>(ah, woh, woh, woh,
                                        out, out, out, INNER_, DM_);

    state_part<<<B_ * H_ * STCH, 256>>>(k, v, beta, alpha_log, stpart);
    state_comb<<<B_ * H_, 256>>>(stpart, alpha_log, out + (size_t)MROWS * DM_);
}

// round 10
// speedup vs baseline: 1.4033x; 1.0044x over previous
#include <cuda_runtime.h>
#include <cuda_fp16.h>
#include <math.h>
#include <stdint.h>

#define B_ 2
#define S_ 2048
#define DM_ 2048
#define H_ 8
#define DH_ 128
#define INNER_ 1024
#define MROWS (B_*S_)   // 4096

// ---------------- scratch (device globals; no allocation allowed) ----------
__device__ float g_q[MROWS * INNER_];
__device__ float g_k[MROWS * INNER_];
__device__ float g_v[MROWS * INNER_];
__device__ float g_beta[MROWS * H_];
__device__ float g_amean[H_];

__device__ __align__(128) __half g_xh[MROWS * DM_];
__device__ __align__(128) __half g_wqh[INNER_ * DM_];
__device__ __align__(128) __half g_wkh[INNER_ * DM_];
__device__ __align__(128) __half g_wvh[INNER_ * DM_];
__device__ __align__(128) __half g_woh[DM_ * INNER_];
__device__ __align__(128) __half g_ah[MROWS * INNER_];

#define STWIN_ 128
#define STCH 4
#define STLEN (STWIN_/STCH)   // 32
__device__ float g_stpart[B_ * H_ * STCH * DH_ * DH_];

__device__ __forceinline__ float sigmoidf_(float x) {
    return 1.0f / (1.0f + expf(-x));
}

// ======================= PTX helpers ==============================
__device__ __forceinline__ uint32_t smem_u32(const void* p) {
    uint32_t a;
    asm("{ .reg .u64 t; cvta.to.shared.u64 t, %1; cvt.u32.u64 %0, t; }"
        : "=r"(a) : "l"(p));
    return a;
}

#define CP_ASYNC16(dst, src) \
    asm volatile("cp.async.cg.shared.global [%0], [%1], 16;" :: "r"(dst), "l"(src) : "memory")
#define CP_COMMIT() asm volatile("cp.async.commit_group;" ::: "memory")
#define CP_WAIT(n)  asm volatile("cp.async.wait_group %0;" :: "n"(n) : "memory")

__device__ __forceinline__ void ldsm_x4(uint32_t& r0, uint32_t& r1, uint32_t& r2, uint32_t& r3,
                                        uint32_t addr) {
    asm volatile("ldmatrix.sync.aligned.m8n8.x4.shared.b16 {%0,%1,%2,%3}, [%4];"
        : "=r"(r0), "=r"(r1), "=r"(r2), "=r"(r3) : "r"(addr));
}

__device__ __forceinline__ void mma16816(float* c, const uint32_t* a, uint32_t b0, uint32_t b1) {
    asm volatile(
        "mma.sync.aligned.m16n8k16.row.col.f32.f16.f16.f32 "
        "{%0,%1,%2,%3}, {%4,%5,%6,%7}, {%8,%9}, {%0,%1,%2,%3};"
        : "+f"(c[0]), "+f"(c[1]), "+f"(c[2]), "+f"(c[3])
        : "r"(a[0]), "r"(a[1]), "r"(a[2]), "r"(a[3]), "r"(b0), "r"(b1));
}

// ======================= conversions ==========================
__global__ void cvt1_kernel(const float* __restrict__ src,
                            __half* __restrict__ dst, int n4) {
    int i = blockIdx.x * blockDim.x + threadIdx.x;
    if (i >= n4) return;
    float4 v = ((const float4*)src)[i];
    __half2* p = (__half2*)dst;
    p[2*i]   = __half2(__float2half(v.x), __float2half(v.y));
    p[2*i+1] = __half2(__float2half(v.z), __float2half(v.w));
}

__global__ void cvt4_kernel(const float* __restrict__ s0, const float* __restrict__ s1,
                            const float* __restrict__ s2, const float* __restrict__ s3,
                            __half* __restrict__ d0, __half* __restrict__ d1,
                            __half* __restrict__ d2, __half* __restrict__ d3, int n4) {
    int i = blockIdx.x * blockDim.x + threadIdx.x;
    if (i >= n4) return;
    int seg = blockIdx.y;
    const float* s = (seg == 0) ? s0 : (seg == 1) ? s1 : (seg == 2) ? s2 : s3;
    __half* d = (seg == 0) ? d0 : (seg == 1) ? d1 : (seg == 2) ? d2 : d3;
    float4 v = ((const float4*)s)[i];
    __half2* p = (__half2*)d;
    p[2*i]   = __half2(__float2half(v.x), __float2half(v.y));
    p[2*i+1] = __half2(__float2half(v.z), __float2half(v.w));
}

// ======================= fp16 1-pass HMMA GEMM ==============================
// C[M,N](fp32) = Ah[M,K] @ Bh[N,K]^T (both single-rounded fp16, fp32 accum)
// 128x128 CTA tile, k-chunk 64 halves (128B), 3-stage cp.async, 2 CTAs/SM.
#define NSTG 3
#define TILE_B 16384u                 // one operand tile: 128 rows x 128B
#define STG_BYTES (2u * TILE_B)       // Ah | Bh = 32KB
#define GEMM_SMEM (NSTG * STG_BYTES)  // 96KB

__global__ __launch_bounds__(256, 2) void hmma_gemm(
    const __half* __restrict__ Ah,
    const __half* __restrict__ B0, const __half* __restrict__ B1,
    const __half* __restrict__ B2,
    float* __restrict__ C0, float* __restrict__ C1, float* __restrict__ C2,
    int K, int ldc) {
    extern __shared__ char smem[];
    uint32_t sm = smem_u32(smem);
    int tid = threadIdx.x;
    int lane = tid & 31;
    int wid = tid >> 5;
    int wm = wid & 1;          // 2 M-blocks of 64
    int wn = wid >> 1;         // 4 N-blocks of 32
    int m0 = blockIdx.y * 128;
    int n0 = blockIdx.x * 128;

    const __half* Bh;
    float* C;
    if (blockIdx.z == 0)      { Bh = B0; C = C0; }
    else if (blockIdx.z == 1) { Bh = B1; C = C1; }
    else                      { Bh = B2; C = C2; }

    int kiters = K >> 6;

    float acc[4][4][4];
    #pragma unroll
    for (int i = 0; i < 4; i++)
        #pragma unroll
        for (int j = 0; j < 4; j++)
            #pragma unroll
            for (int t = 0; t < 4; t++) acc[i][j][t] = 0.f;

    int lc = tid & 7;          // 16B chunk col within 128B row
    int lr = tid >> 3;         // 0..31

    #define ISSUE_STAGE(ip, buf) do {                                          \
        int _k0 = (ip) << 6;                                                   \
        const __half* _ah = Ah + (size_t)(m0 + lr) * K + _k0 + lc * 8;         \
        const __half* _bh = Bh + (size_t)(n0 + lr) * K + _k0 + lc * 8;         \
        uint32_t _sb = sm + (buf) * STG_BYTES;                                 \
        _Pragma("unroll")                                                      \
        for (int _i = 0; _i < 4; _i++) {                                       \
            int _row = lr + 32 * _i;                                           \
            uint32_t _sw = ((uint32_t)_row << 7) + (((uint32_t)(lc ^ (_row & 7))) << 4); \
            size_t _go = (size_t)(32 * _i) * K;                                \
            CP_ASYNC16(_sb + _sw,          _ah + _go);                         \
            CP_ASYNC16(_sb + TILE_B + _sw, _bh + _go);                         \
        }                                                                      \
    } while (0)

    ISSUE_STAGE(0, 0); CP_COMMIT();
    if (kiters > 1) ISSUE_STAGE(1, 1);
    CP_COMMIT();

    int buf = 0;
    int ibuf = 2;
    for (int it = 0; it < kiters; ++it) {
        if (it + 2 < kiters) ISSUE_STAGE(it + 2, ibuf);
        CP_COMMIT();
        CP_WAIT(2);
        __syncthreads();

        uint32_t sah = sm + buf * STG_BYTES;
        uint32_t sbh = sah + TILE_B;
        #pragma unroll
        for (int ks = 0; ks < 4; ++ks) {
            int ch = ks * 2 + (lane >> 4);
            uint32_t bfr[2][4];
            #pragma unroll
            for (int nt2 = 0; nt2 < 2; ++nt2) {
                int rowB = wn * 32 + nt2 * 16 + (lane & 7) + ((lane >> 3) & 1) * 8;
                uint32_t off = ((uint32_t)rowB << 7) + (((uint32_t)(ch ^ (rowB & 7))) << 4);
                ldsm_x4(bfr[nt2][0], bfr[nt2][1], bfr[nt2][2], bfr[nt2][3], sbh + off);
            }
            #pragma unroll
            for (int mt = 0; mt < 4; ++mt) {
                int rowA = wm * 64 + mt * 16 + (lane & 7) + ((lane >> 3) & 1) * 8;
                uint32_t off = ((uint32_t)rowA << 7) + (((uint32_t)(ch ^ (rowA & 7))) << 4);
                uint32_t a[4];
                ldsm_x4(a[0], a[1], a[2], a[3], sah + off);
                #pragma unroll
                for (int nt2 = 0; nt2 < 2; ++nt2) {
                    mma16816(acc[mt][nt2 * 2 + 0], a, bfr[nt2][0], bfr[nt2][2]);
                    mma16816(acc[mt][nt2 * 2 + 1], a, bfr[nt2][1], bfr[nt2][3]);
                }
            }
        }
        __syncthreads();
        buf = (buf == 2) ? 0 : buf + 1;
        ibuf = (ibuf == 2) ? 0 : ibuf + 1;
    }
    #undef ISSUE_STAGE

    // -------- epilogue --------
    #pragma unroll
    for (int mt = 0; mt < 4; ++mt) {
        int m = m0 + wm * 64 + mt * 16 + (lane >> 2);
        #pragma unroll
        for (int nt = 0; nt < 4; ++nt) {
            int n = n0 + wn * 32 + nt * 8 + (lane & 3) * 2;
            float* p = C + (size_t)m * ldc + n;
            *(float2*)p = make_float2(acc[mt][nt][0], acc[mt][nt][1]);
            *(float2*)(p + 8 * (size_t)ldc) = make_float2(acc[mt][nt][2], acc[mt][nt][3]);
        }
    }
}

// ---------------- alpha_mean per head ----------------
__global__ void amean_kernel(const float* __restrict__ alpha_log) {
    int w = threadIdx.x >> 5;
    int lane = threadIdx.x & 31;
    float s = 0.f;
    for (int d = lane; d < DH_; d += 32)
        s += sigmoidf_(alpha_log[w * DH_ + d]);
    #pragma unroll
    for (int o = 16; o; o >>= 1) s += __shfl_xor_sync(0xffffffffu, s, o);
    if (lane == 0) g_amean[w] = s / (float)DH_;
}

// ---------------- beta = sigmoid(x @ Wb^T + bb) ----------------
__global__ __launch_bounds__(256) void beta_kernel(const float* __restrict__ x,
                                                   const float* __restrict__ Wb,
                                                   const float* __restrict__ bb,
                                                   float* __restrict__ beta) {
    __shared__ float xs[DM_];
    int row = blockIdx.x;
    for (int i = threadIdx.x; i < DM_; i += 256)
        xs[i] = x[row * DM_ + i];
    __syncthreads();
    int w = threadIdx.x >> 5;
    int lane = threadIdx.x & 31;
    const float* wr = Wb + w * DM_;
    float sum = 0.f;
    for (int i = lane; i < DM_; i += 32)
        sum += xs[i] * wr[i];
    #pragma unroll
    for (int o = 16; o; o >>= 1) sum += __shfl_xor_sync(0xffffffffu, sum, o);
    if (lane == 0) beta[row * H_ + w] = sigmoidf_(sum + bb[w]);
}

// ---------------- RoPE in-place on q and k ----------------
__global__ void rope_kernel(float* __restrict__ q, float* __restrict__ k) {
    int idx = blockIdx.x * blockDim.x + threadIdx.x;
    int j = idx & 63;
    int h = (idx >> 6) & (H_ - 1);
    int row = idx >> 9;
    int s = row & (S_ - 1);
    float ex = (float)(2 * j) * (1.0f / (float)DH_);
    float inv = powf(10000.0f, -ex);
    float ang = (float)s * inv;
    float sn, c;
    sincosf(ang, &sn, &c);
    int base = row * INNER_ + h * DH_ + j;
    float x1 = q[base], x2 = q[base + 64];
    q[base]      = x1 * c - x2 * sn;
    q[base + 64] = x2 * c + x1 * sn;
    x1 = k[base]; x2 = k[base + 64];
    k[base]      = x1 * c - x2 * sn;
    k[base + 64] = x2 * c + x1 * sn;
}

// ---------------- windowed decay attention (4-way ILP, emits fp16) ---------
#define WIN_ 32
__global__ __launch_bounds__(256) void attn_kernel(const float* __restrict__ q,
                                                   const float* __restrict__ k,
                                                   const float* __restrict__ v,
                                                   const float* __restrict__ beta,
                                                   __half* __restrict__ ah) {
    int gw = (blockIdx.x * 256 + threadIdx.x) >> 5;
    int lane = threadIdx.x & 31;
    int s = gw & (S_ - 1);
    int h = (gw >> 11) & (H_ - 1);
    int b = gw >> 14;
    float am = g_amean[h];
    float am2 = am * am;
    float am3 = am2 * am;
    float am4 = am2 * am2;
    size_t colbase = (size_t)b * S_ * INNER_ + h * DH_ + lane * 4;
    const float4 qv = *(const float4*)(q + colbase + (size_t)s * INNER_);
    float4 acc = make_float4(0.f, 0.f, 0.f, 0.f);
    float decay = 1.f;
    int t_lo = s - (WIN_ - 1); if (t_lo < 0) t_lo = 0;
    const float* betab = beta + (size_t)b * S_ * H_ + h;

    for (int t4 = s; t4 >= t_lo; t4 -= 4) {
        int t1 = t4 - 1, t2 = t4 - 2, t3 = t4 - 3;
        bool m1 = t1 >= t_lo, m2 = t2 >= t_lo, m3 = t3 >= t_lo;
        float4 z = make_float4(0.f, 0.f, 0.f, 0.f);
        float4 k0 = *(const float4*)(k + colbase + (size_t)t4 * INNER_);
        float4 v0 = *(const float4*)(v + colbase + (size_t)t4 * INNER_);
        float4 k1 = m1 ? *(const float4*)(k + colbase + (size_t)t1 * INNER_) : z;
        float4 v1 = m1 ? *(const float4*)(v + colbase + (size_t)t1 * INNER_) : z;
        float4 k2 = m2 ? *(const float4*)(k + colbase + (size_t)t2 * INNER_) : z;
        float4 v2 = m2 ? *(const float4*)(v + colbase + (size_t)t2 * INNER_) : z;
        float4 k3 = m3 ? *(const float4*)(k + colbase + (size_t)t3 * INNER_) : z;
        float4 v3 = m3 ? *(const float4*)(v + colbase + (size_t)t3 * INNER_) : z;
        float d0 = qv.x*k0.x + qv.y*k0.y + qv.z*k0.z + qv.w*k0.w;
        float d1 = qv.x*k1.x + qv.y*k1.y + qv.z*k1.z + qv.w*k1.w;
        float d2 = qv.x*k2.x + qv.y*k2.y + qv.z*k2.z + qv.w*k2.w;
        float d3 = qv.x*k3.x + qv.y*k3.y + qv.z*k3.z + qv.w*k3.w;
        #pragma unroll
        for (int o = 16; o; o >>= 1) {
            d0 += __shfl_xor_sync(0xffffffffu, d0, o);
            d1 += __shfl_xor_sync(0xffffffffu, d1, o);
            d2 += __shfl_xor_sync(0xffffffffu, d2, o);
            d3 += __shfl_xor_sync(0xffffffffu, d3, o);
        }
        float bt0 = betab[(size_t)t4 * H_];
        float bt1 = m1 ? betab[(size_t)t1 * H_] : 0.f;
        float bt2 = m2 ? betab[(size_t)t2 * H_] : 0.f;
        float bt3 = m3 ? betab[(size_t)t3 * H_] : 0.f;
        float w0 = d0 * decay * bt0;
        float w1 = d1 * decay * am  * bt1;
        float w2 = d2 * decay * am2 * bt2;
        float w3 = d3 * decay * am3 * bt3;
        acc.x = fmaf(w0, v0.x, fmaf(w1, v1.x, fmaf(w2, v2.x, fmaf(w3, v3.x, acc.x))));
        acc.y = fmaf(w0, v0.y, fmaf(w1, v1.y, fmaf(w2, v2.y, fmaf(w3, v3.y, acc.y))));
        acc.z = fmaf(w0, v0.z, fmaf(w1, v1.z, fmaf(w2, v2.z, fmaf(w3, v3.z, acc.z))));
        acc.w = fmaf(w0, v0.w, fmaf(w1, v1.w, fmaf(w2, v2.w, fmaf(w3, v3.w, acc.w))));
        decay *= am4;
    }
    size_t o = colbase + (size_t)s * INNER_;
    ((__half2*)(ah + o))[0] = __half2(__float2half(acc.x), __float2half(acc.y));
    ((__half2*)(ah + o))[1] = __half2(__float2half(acc.z), __float2half(acc.w));
}

// ---------------- recurrent state: partial chunks + combine ----------------
__global__ __launch_bounds__(256) void state_part(const float* __restrict__ k,
                                                  const float* __restrict__ v,
                                                  const float* __restrict__ beta,
                                                  const float* __restrict__ alpha_log,
                                                  float* __restrict__ part) {
    int bh = blockIdx.x >> 2;
    int c  = blockIdx.x & 3;
    int b = bh >> 3;
    int h = bh & 7;
    int tid = threadIdx.x;
    int d = tid >> 1;
    int e0 = (tid & 1) * 64;
    __shared__ float ks[DH_], vs[DH_];
    float st[64];
    #pragma unroll
    for (int e = 0; e < 64; e++) st[e] = 0.f;
    float ad = sigmoidf_(alpha_log[h * DH_ + d]);
    int tbeg = S_ - STWIN_ + c * STLEN;
    for (int t = tbeg; t < tbeg + STLEN; t++) {
        __syncthreads();
        size_t base = (size_t)(b * S_ + t) * INNER_ + h * DH_;
        if (tid < 128) ks[tid] = k[base + tid];
        else           vs[tid - 128] = v[base + tid - 128];
        __syncthreads();
        float kb = ks[d] * beta[(b * S_ + t) * H_ + h];
        #pragma unroll
        for (int e = 0; e < 64; e++)
            st[e] = fmaf(ad, st[e], kb * vs[e0 + e]);
    }
    float* op = part + (((size_t)bh * STCH + c) * DH_ + d) * DH_ + e0;
    #pragma unroll
    for (int e = 0; e < 64; e++) op[e] = st[e];
}

__global__ __launch_bounds__(256) void state_comb(const float* __restrict__ part,
                                                  const float* __restrict__ alpha_log,
                                                  float* __restrict__ stout) {
    int bh = blockIdx.x;
    int h = bh & 7;
    int tid = threadIdx.x;
    int d = tid >> 1;
    int e0 = (tid & 1) * 64;
    float ad = sigmoidf_(alpha_log[h * DH_ + d]);
    float a32 = ad;
    a32 *= a32; a32 *= a32; a32 *= a32; a32 *= a32; a32 *= a32;
    const float* p0 = part + (((size_t)bh * STCH + 0) * DH_ + d) * DH_ + e0;
    const float* p1 = part + (((size_t)bh * STCH + 1) * DH_ + d) * DH_ + e0;
    const float* p2 = part + (((size_t)bh * STCH + 2) * DH_ + d) * DH_ + e0;
    const float* p3 = part + (((size_t)bh * STCH + 3) * DH_ + d) * DH_ + e0;
    float* op = stout + ((size_t)bh * DH_ + d) * DH_ + e0;
    #pragma unroll
    for (int e = 0; e < 64; e++) {
        float r = p0[e];
        r = fmaf(r, a32, p1[e]);
        r = fmaf(r, a32, p2[e]);
        r = fmaf(r, a32, p3[e]);
        op[e] = r;
    }
}

// ---------------- launch ----------------
extern "C" void kernel_launch(void* const* d_in, const int* in_sizes, int n_in,
                              void* d_out, int out_size) {
    const float* x         = (const float*)d_in[0];
    const float* Wq        = (const float*)d_in[1];
    const float* Wk        = (const float*)d_in[2];
    const float* Wv        = (const float*)d_in[3];
    const float* Wo        = (const float*)d_in[4];
    const float* Wb        = (const float*)d_in[5];
    const float* bb        = (const float*)d_in[6];
    const float* alpha_log = (const float*)d_in[7];
    float* out = (float*)d_out;

    float *q, *k, *v, *beta, *stpart;
    cudaGetSymbolAddress((void**)&q,      g_q);
    cudaGetSymbolAddress((void**)&k,      g_k);
    cudaGetSymbolAddress((void**)&v,      g_v);
    cudaGetSymbolAddress((void**)&beta,   g_beta);
    cudaGetSymbolAddress((void**)&stpart, g_stpart);
    __half *xh, *wqh, *wkh, *wvh, *woh, *ah;
    cudaGetSymbolAddress((void**)&xh,  g_xh);
    cudaGetSymbolAddress((void**)&wqh, g_wqh);
    cudaGetSymbolAddress((void**)&wkh, g_wkh);
    cudaGetSymbolAddress((void**)&wvh, g_wvh);
    cudaGetSymbolAddress((void**)&woh, g_woh);
    cudaGetSymbolAddress((void**)&ah,  g_ah);

    cudaFuncSetAttribute(hmma_gemm, cudaFuncAttributeMaxDynamicSharedMemorySize, GEMM_SMEM);

    amean_kernel<<<1, 256>>>(alpha_log);
    beta_kernel<<<MROWS, 256>>>(x, Wb, bb, beta);

    cvt1_kernel<<<(MROWS*DM_/4 + 255)/256, 256>>>(x, xh, MROWS*DM_/4);
    dim3 gcvt((INNER_*DM_/4 + 255)/256, 4);
    cvt4_kernel<<<gcvt, 256>>>(Wq, Wk, Wv, Wo, wqh, wkh, wvh, woh, INNER_*DM_/4);

    // QKV: fused 3-way GEMM, M=4096, N=1024, K=2048
    dim3 gqkv(INNER_/128, MROWS/128, 3);
    hmma_gemm<<<gqkv, 256, GEMM_SMEM>>>(xh, wqh, wkh, wvh,
                                        q, k, v, DM_, INNER_);

    rope_kernel<<<(B_ * S_ * H_ * 64) / 256, 256>>>(q, k);
    attn_kernel<<<(B_ * H_ * S_) / 8, 256>>>(q, k, v, beta, ah);

    // O-proj: M=4096, N=2048, K=1024
    dim3 gout(DM_/128, MROWS/128, 1);
    hmma_gemm<<<gout, 256, GEMM_SMEM>>>(ah, woh, woh, woh,
                                        out, out, out, INNER_, DM_);

    state_part<<<B_ * H_ * STCH, 256>>>(k, v, beta, alpha_log, stpart);
    state_comb<<<B_ * H_, 256>>>(stpart, alpha_log, out + (size_t)MROWS * DM_);
}

// round 11
// speedup vs baseline: 1.4124x; 1.0065x over previous
#include <cuda_runtime.h>
#include <cuda_fp16.h>
#include <math.h>
#include <stdint.h>

#define B_ 2
#define S_ 2048
#define DM_ 2048
#define H_ 8
#define DH_ 128
#define INNER_ 1024
#define MROWS (B_*S_)   // 4096

// ---------------- scratch (device globals; no allocation allowed) ----------
__device__ float g_q[MROWS * INNER_];
__device__ float g_k[MROWS * INNER_];
__device__ float g_v[MROWS * INNER_];
__device__ float g_beta[MROWS * H_];
__device__ float g_amean[H_];
__device__ float g_ctab[S_ * 64];
__device__ float g_stab[S_ * 64];

__device__ __align__(128) __half g_xh[MROWS * DM_];
__device__ __align__(128) __half g_wqh[INNER_ * DM_];
__device__ __align__(128) __half g_wkh[INNER_ * DM_];
__device__ __align__(128) __half g_wvh[INNER_ * DM_];
__device__ __align__(128) __half g_woh[DM_ * INNER_];
__device__ __align__(128) __half g_ah[MROWS * INNER_];

#define STWIN_ 128
#define STCH 4
#define STLEN (STWIN_/STCH)   // 32
__device__ float g_stpart[B_ * H_ * STCH * DH_ * DH_];

__device__ __forceinline__ float sigmoidf_(float x) {
    return 1.0f / (1.0f + expf(-x));
}

// ======================= PTX helpers ==============================
__device__ __forceinline__ uint32_t smem_u32(const void* p) {
    uint32_t a;
    asm("{ .reg .u64 t; cvta.to.shared.u64 t, %1; cvt.u32.u64 %0, t; }"
        : "=r"(a) : "l"(p));
    return a;
}

#define CP_ASYNC16(dst, src) \
    asm volatile("cp.async.cg.shared.global [%0], [%1], 16;" :: "r"(dst), "l"(src) : "memory")
#define CP_COMMIT() asm volatile("cp.async.commit_group;" ::: "memory")
#define CP_WAIT(n)  asm volatile("cp.async.wait_group %0;" :: "n"(n) : "memory")

__device__ __forceinline__ void ldsm_x4(uint32_t& r0, uint32_t& r1, uint32_t& r2, uint32_t& r3,
                                        uint32_t addr) {
    asm volatile("ldmatrix.sync.aligned.m8n8.x4.shared.b16 {%0,%1,%2,%3}, [%4];"
        : "=r"(r0), "=r"(r1), "=r"(r2), "=r"(r3) : "r"(addr));
}

__device__ __forceinline__ void mma16816(float* c, const uint32_t* a, uint32_t b0, uint32_t b1) {
    asm volatile(
        "mma.sync.aligned.m16n8k16.row.col.f32.f16.f16.f32 "
        "{%0,%1,%2,%3}, {%4,%5,%6,%7}, {%8,%9}, {%0,%1,%2,%3};"
        : "+f"(c[0]), "+f"(c[1]), "+f"(c[2]), "+f"(c[3])
        : "r"(a[0]), "r"(a[1]), "r"(a[2]), "r"(a[3]), "r"(b0), "r"(b1));
}

// ======================= rope cos/sin table ==========================
__global__ void ropetab_kernel(float* __restrict__ ct, float* __restrict__ st) {
    int idx = blockIdx.x * blockDim.x + threadIdx.x;   // < S_*64
    int j = idx & 63;
    int s = idx >> 6;
    float ex = (float)(2 * j) * (1.0f / (float)DH_);
    float inv = powf(10000.0f, -ex);
    float sn, c;
    sincosf((float)s * inv, &sn, &c);
    ct[idx] = c;
    st[idx] = sn;
}

// ======================= x prep: fp16 convert + beta =======================
__global__ __launch_bounds__(256) void xprep_kernel(const float* __restrict__ x,
                                                    const float* __restrict__ Wb,
                                                    const float* __restrict__ bb,
                                                    __half* __restrict__ xh,
                                                    float* __restrict__ beta) {
    __shared__ float xs[DM_];
    int row = blockIdx.x;
    const float4* src = (const float4*)(x + (size_t)row * DM_);
    __half2* dst = (__half2*)(xh + (size_t)row * DM_);
    for (int i = threadIdx.x; i < DM_/4; i += 256) {
        float4 v = src[i];
        *(float4*)&xs[i*4] = v;
        dst[2*i]   = __half2(__float2half(v.x), __float2half(v.y));
        dst[2*i+1] = __half2(__float2half(v.z), __float2half(v.w));
    }
    __syncthreads();
    int w = threadIdx.x >> 5;
    int lane = threadIdx.x & 31;
    const float* wr = Wb + w * DM_;
    float sum = 0.f;
    for (int i = lane; i < DM_; i += 32)
        sum += xs[i] * wr[i];
    #pragma unroll
    for (int o = 16; o; o >>= 1) sum += __shfl_xor_sync(0xffffffffu, sum, o);
    if (lane == 0) beta[row * H_ + w] = sigmoidf_(sum + bb[w]);
}

// fp32 -> fp16 for all four weight matrices (same element count each)
__global__ void cvt4_kernel(const float* __restrict__ s0, const float* __restrict__ s1,
                            const float* __restrict__ s2, const float* __restrict__ s3,
                            __half* __restrict__ d0, __half* __restrict__ d1,
                            __half* __restrict__ d2, __half* __restrict__ d3, int n4) {
    int i = blockIdx.x * blockDim.x + threadIdx.x;
    if (i >= n4) return;
    int seg = blockIdx.y;
    const float* s = (seg == 0) ? s0 : (seg == 1) ? s1 : (seg == 2) ? s2 : s3;
    __half* d = (seg == 0) ? d0 : (seg == 1) ? d1 : (seg == 2) ? d2 : d3;
    float4 v = ((const float4*)s)[i];
    __half2* p = (__half2*)d;
    p[2*i]   = __half2(__float2half(v.x), __float2half(v.y));
    p[2*i+1] = __half2(__float2half(v.z), __float2half(v.w));
}

// ======================= fp16 1-pass HMMA GEMM ==============================
// C[M,N](fp32) = Ah[M,K] @ Bh[N,K]^T. 128x128 CTA tile, k-chunk 64 halves,
// 3-stage cp.async, ONE sync per chunk, 2 CTAs/SM.
#define NSTG 3
#define TILE_B 16384u
#define STG_BYTES (2u * TILE_B)       // Ah | Bh = 32KB
#define GEMM_SMEM (NSTG * STG_BYTES)  // 96KB

__global__ __launch_bounds__(256, 2) void hmma_gemm(
    const __half* __restrict__ Ah,
    const __half* __restrict__ B0, const __half* __restrict__ B1,
    const __half* __restrict__ B2,
    float* __restrict__ C0, float* __restrict__ C1, float* __restrict__ C2,
    int K, int ldc) {
    extern __shared__ char smem[];
    uint32_t sm = smem_u32(smem);
    int tid = threadIdx.x;
    int lane = tid & 31;
    int wid = tid >> 5;
    int wm = wid & 1;
    int wn = wid >> 1;
    int m0 = blockIdx.y * 128;
    int n0 = blockIdx.x * 128;

    const __half* Bh;
    float* C;
    if (blockIdx.z == 0)      { Bh = B0; C = C0; }
    else if (blockIdx.z == 1) { Bh = B1; C = C1; }
    else                      { Bh = B2; C = C2; }

    int kiters = K >> 6;

    float acc[4][4][4];
    #pragma unroll
    for (int i = 0; i < 4; i++)
        #pragma unroll
        for (int j = 0; j < 4; j++)
            #pragma unroll
            for (int t = 0; t < 4; t++) acc[i][j][t] = 0.f;

    int lc = tid & 7;
    int lr = tid >> 3;

    #define ISSUE_STAGE(ip, buf) do {                                          \
        int _k0 = (ip) << 6;                                                   \
        const __half* _ah = Ah + (size_t)(m0 + lr) * K + _k0 + lc * 8;         \
        const __half* _bh = Bh + (size_t)(n0 + lr) * K + _k0 + lc * 8;         \
        uint32_t _sb = sm + (buf) * STG_BYTES;                                 \
        _Pragma("unroll")                                                      \
        for (int _i = 0; _i < 4; _i++) {                                       \
            int _row = lr + 32 * _i;                                           \
            uint32_t _sw = ((uint32_t)_row << 7) + (((uint32_t)(lc ^ (_row & 7))) << 4); \
            size_t _go = (size_t)(32 * _i) * K;                                \
            CP_ASYNC16(_sb + _sw,          _ah + _go);                         \
            CP_ASYNC16(_sb + TILE_B + _sw, _bh + _go);                         \
        }                                                                      \
    } while (0)

    ISSUE_STAGE(0, 0); CP_COMMIT();
    ISSUE_STAGE(1, 1); CP_COMMIT();

    for (int it = 0; it < kiters; ++it) {
        if (it + 1 < kiters) { CP_WAIT(1); } else { CP_WAIT(0); }
        __syncthreads();
        if (it + 2 < kiters) {
            int nb = it + 2; while (nb >= 3) nb -= 3;
            ISSUE_STAGE(it + 2, nb);
            CP_COMMIT();
        }
        int cb = it; while (cb >= 3) cb -= 3;
        uint32_t sah = sm + cb * STG_BYTES;
        uint32_t sbh = sah + TILE_B;
        #pragma unroll
        for (int ks = 0; ks < 4; ++ks) {
            int ch = ks * 2 + (lane >> 4);
            uint32_t bfr[2][4];
            #pragma unroll
            for (int nt2 = 0; nt2 < 2; ++nt2) {
                int rowB = wn * 32 + nt2 * 16 + (lane & 7) + ((lane >> 3) & 1) * 8;
                uint32_t off = ((uint32_t)rowB << 7) + (((uint32_t)(ch ^ (rowB & 7))) << 4);
                ldsm_x4(bfr[nt2][0], bfr[nt2][1], bfr[nt2][2], bfr[nt2][3], sbh + off);
            }
            #pragma unroll
            for (int mt = 0; mt < 4; ++mt) {
                int rowA = wm * 64 + mt * 16 + (lane & 7) + ((lane >> 3) & 1) * 8;
                uint32_t off = ((uint32_t)rowA << 7) + (((uint32_t)(ch ^ (rowA & 7))) << 4);
                uint32_t a[4];
                ldsm_x4(a[0], a[1], a[2], a[3], sah + off);
                #pragma unroll
                for (int nt2 = 0; nt2 < 2; ++nt2) {
                    mma16816(acc[mt][nt2 * 2 + 0], a, bfr[nt2][0], bfr[nt2][2]);
                    mma16816(acc[mt][nt2 * 2 + 1], a, bfr[nt2][1], bfr[nt2][3]);
                }
            }
        }
    }
    #undef ISSUE_STAGE

    // -------- epilogue --------
    #pragma unroll
    for (int mt = 0; mt < 4; ++mt) {
        int m = m0 + wm * 64 + mt * 16 + (lane >> 2);
        #pragma unroll
        for (int nt = 0; nt < 4; ++nt) {
            int n = n0 + wn * 32 + nt * 8 + (lane & 3) * 2;
            float* p = C + (size_t)m * ldc + n;
            *(float2*)p = make_float2(acc[mt][nt][0], acc[mt][nt][1]);
            *(float2*)(p + 8 * (size_t)ldc) = make_float2(acc[mt][nt][2], acc[mt][nt][3]);
        }
    }
}

// ---------------- alpha_mean per head ----------------
__global__ void amean_kernel(const float* __restrict__ alpha_log) {
    int w = threadIdx.x >> 5;
    int lane = threadIdx.x & 31;
    float s = 0.f;
    for (int d = lane; d < DH_; d += 32)
        s += sigmoidf_(alpha_log[w * DH_ + d]);
    #pragma unroll
    for (int o = 16; o; o >>= 1) s += __shfl_xor_sync(0xffffffffu, s, o);
    if (lane == 0) g_amean[w] = s / (float)DH_;
}

// ---------------- smem-tiled windowed decay attention with fused RoPE ------
// Block: 8 warps = 8 consecutive s for one (b,h). Stages 39 k/v rows in smem,
// ropes k in-place, ropes q per warp. Emits fp16.
#define WIN_ 32
#define ATT_S 8
#define ATT_ROWS (WIN_ - 1 + ATT_S)   // 39
__global__ __launch_bounds__(256) void attn_kernel(const float* __restrict__ q,
                                                   const float* __restrict__ k,
                                                   const float* __restrict__ v,
                                                   const float* __restrict__ beta,
                                                   const float* __restrict__ ctab,
                                                   const float* __restrict__ stab,
                                                   __half* __restrict__ ah) {
    __shared__ float ks[ATT_ROWS * DH_];
    __shared__ float vs[ATT_ROWS * DH_];
    __shared__ float bs[ATT_ROWS];
    int tid = threadIdx.x;
    int wid = tid >> 5;
    int lane = tid & 31;
    int s0 = blockIdx.x * ATT_S;
    int h  = blockIdx.y;
    int b  = blockIdx.z;
    int base_t = s0 - (WIN_ - 1);     // may be negative

    size_t bh = (size_t)b * S_ * INNER_ + h * DH_;

    // stage raw k/v + beta
    for (int i = tid; i < ATT_ROWS * 32; i += 256) {
        int r = i >> 5;
        int c = (i & 31) * 4;
        int t = base_t + r;
        float4 z = make_float4(0.f, 0.f, 0.f, 0.f);
        float4 kv = z, vv = z;
        if (t >= 0) {
            kv = *(const float4*)(k + bh + (size_t)t * INNER_ + c);
            vv = *(const float4*)(v + bh + (size_t)t * INNER_ + c);
        }
        *(float4*)&ks[r * DH_ + c] = kv;
        *(float4*)&vs[r * DH_ + c] = vv;
    }
    if (tid < ATT_ROWS) {
        int t = base_t + tid;
        bs[tid] = (t >= 0) ? beta[(size_t)(b * S_ + t) * H_ + h] : 0.f;
    }
    __syncthreads();

    // rope k in place (each item owns a (c, c+64) pair)
    for (int i = tid; i < ATT_ROWS * 16; i += 256) {
        int r = i >> 4;
        int c = (i & 15) * 4;         // 0..60
        int t = base_t + r;
        if (t < 0) continue;
        float4 a = *(float4*)&ks[r * DH_ + c];
        float4 p = *(float4*)&ks[r * DH_ + c + 64];
        float4 ct4 = *(const float4*)&ctab[(size_t)t * 64 + c];
        float4 st4 = *(const float4*)&stab[(size_t)t * 64 + c];
        float4 lo, hi;
        lo.x = a.x*ct4.x - p.x*st4.x;  hi.x = p.x*ct4.x + a.x*st4.x;
        lo.y = a.y*ct4.y - p.y*st4.y;  hi.y = p.y*ct4.y + a.y*st4.y;
        lo.z = a.z*ct4.z - p.z*st4.z;  hi.z = p.z*ct4.z + a.z*st4.z;
        lo.w = a.w*ct4.w - p.w*st4.w;  hi.w = p.w*ct4.w + a.w*st4.w;
        *(float4*)&ks[r * DH_ + c]      = lo;
        *(float4*)&ks[r * DH_ + c + 64] = hi;
    }
    __syncthreads();

    int s = s0 + wid;
    float am = g_amean[h];
    float am2 = am * am;
    float am3 = am2 * am;
    float am4 = am2 * am2;
    int c4 = lane * 4;

    // load + rope q (partner lane = lane^16)
    float4 qraw = *(const float4*)(q + bh + (size_t)s * INNER_ + c4);
    int jj = (lane & 15) * 4;
    float4 ct4 = *(const float4*)&ctab[(size_t)s * 64 + jj];
    float4 st4 = *(const float4*)&stab[(size_t)s * 64 + jj];
    float px = __shfl_xor_sync(0xffffffffu, qraw.x, 16);
    float py = __shfl_xor_sync(0xffffffffu, qraw.y, 16);
    float pz = __shfl_xor_sync(0xffffffffu, qraw.z, 16);
    float pw = __shfl_xor_sync(0xffffffffu, qraw.w, 16);
    float4 qv;
    if (lane < 16) {
        qv.x = qraw.x*ct4.x - px*st4.x;
        qv.y = qraw.y*ct4.y - py*st4.y;
        qv.z = qraw.z*ct4.z - pz*st4.z;
        qv.w = qraw.w*ct4.w - pw*st4.w;
    } else {
        qv.x = qraw.x*ct4.x + px*st4.x;
        qv.y = qraw.y*ct4.y + py*st4.y;
        qv.z = qraw.z*ct4.z + pz*st4.z;
        qv.w = qraw.w*ct4.w + pw*st4.w;
    }

    float4 acc = make_float4(0.f, 0.f, 0.f, 0.f);
    float decay = 1.f;
    int t_lo = s - (WIN_ - 1); if (t_lo < 0) t_lo = 0;

    for (int t4 = s; t4 >= t_lo; t4 -= 4) {
        int r0 = t4 - base_t;
        bool m1 = t4 - 1 >= t_lo, m2 = t4 - 2 >= t_lo, m3 = t4 - 3 >= t_lo;
        float4 z = make_float4(0.f, 0.f, 0.f, 0.f);
        float4 k0 = *(const float4*)&ks[r0 * DH_ + c4];
        float4 v0 = *(const float4*)&vs[r0 * DH_ + c4];
        float4 k1 = m1 ? *(const float4*)&ks[(r0-1) * DH_ + c4] : z;
        float4 v1 = m1 ? *(const float4*)&vs[(r0-1) * DH_ + c4] : z;
        float4 k2 = m2 ? *(const float4*)&ks[(r0-2) * DH_ + c4] : z;
        float4 v2 = m2 ? *(const float4*)&vs[(r0-2) * DH_ + c4] : z;
        float4 k3 = m3 ? *(const float4*)&ks[(r0-3) * DH_ + c4] : z;
        float4 v3 = m3 ? *(const float4*)&vs[(r0-3) * DH_ + c4] : z;
        float d0 = qv.x*k0.x + qv.y*k0.y + qv.z*k0.z + qv.w*k0.w;
        float d1 = qv.x*k1.x + qv.y*k1.y + qv.z*k1.z + qv.w*k1.w;
        float d2 = qv.x*k2.x + qv.y*k2.y + qv.z*k2.z + qv.w*k2.w;
        float d3 = qv.x*k3.x + qv.y*k3.y + qv.z*k3.z + qv.w*k3.w;
        #pragma unroll
        for (int o = 16; o; o >>= 1) {
            d0 += __shfl_xor_sync(0xffffffffu, d0, o);
            d1 += __shfl_xor_sync(0xffffffffu, d1, o);
            d2 += __shfl_xor_sync(0xffffffffu, d2, o);
            d3 += __shfl_xor_sync(0xffffffffu, d3, o);
        }
        float w0 = d0 * decay * bs[r0];
        float w1 = m1 ? d1 * decay * am  * bs[r0-1] : 0.f;
        float w2 = m2 ? d2 * decay * am2 * bs[r0-2] : 0.f;
        float w3 = m3 ? d3 * decay * am3 * bs[r0-3] : 0.f;
        acc.x = fmaf(w0, v0.x, fmaf(w1, v1.x, fmaf(w2, v2.x, fmaf(w3, v3.x, acc.x))));
        acc.y = fmaf(w0, v0.y, fmaf(w1, v1.y, fmaf(w2, v2.y, fmaf(w3, v3.y, acc.y))));
        acc.z = fmaf(w0, v0.z, fmaf(w1, v1.z, fmaf(w2, v2.z, fmaf(w3, v3.z, acc.z))));
        acc.w = fmaf(w0, v0.w, fmaf(w1, v1.w, fmaf(w2, v2.w, fmaf(w3, v3.w, acc.w))));
        decay *= am4;
    }
    size_t o = bh + (size_t)s * INNER_ + c4;
    ((__half2*)(ah + o))[0] = __half2(__float2half(acc.x), __float2half(acc.y));
    ((__half2*)(ah + o))[1] = __half2(__float2half(acc.z), __float2half(acc.w));
}

// ---------------- recurrent state: partial chunks + combine ----------------
__global__ __launch_bounds__(256) void state_part(const float* __restrict__ k,
                                                  const float* __restrict__ v,
                                                  const float* __restrict__ beta,
                                                  const float* __restrict__ alpha_log,
                                                  const float* __restrict__ ctab,
                                                  const float* __restrict__ stab,
                                                  float* __restrict__ part) {
    int bh = blockIdx.x >> 2;
    int c  = blockIdx.x & 3;
    int b = bh >> 3;
    int h = bh & 7;
    int tid = threadIdx.x;
    int d = tid >> 1;
    int e0 = (tid & 1) * 64;
    __shared__ float ks[DH_], vs[DH_];
    float st[64];
    #pragma unroll
    for (int e = 0; e < 64; e++) st[e] = 0.f;
    float ad = sigmoidf_(alpha_log[h * DH_ + d]);
    int tbeg = S_ - STWIN_ + c * STLEN;
    for (int t = tbeg; t < tbeg + STLEN; t++) {
        __syncthreads();
        size_t base = (size_t)(b * S_ + t) * INNER_ + h * DH_;
        if (tid < 128) ks[tid] = k[base + tid];
        else           vs[tid - 128] = v[base + tid - 128];
        __syncthreads();
        // rope k element d from smem
        float cv = ctab[(size_t)t * 64 + (d & 63)];
        float sv = stab[(size_t)t * 64 + (d & 63)];
        float kd = (d < 64) ? ks[d] * cv - ks[d + 64] * sv
                            : ks[d] * cv + ks[d - 64] * sv;
        float kb = kd * beta[(b * S_ + t) * H_ + h];
        #pragma unroll
        for (int e = 0; e < 64; e++)
            st[e] = fmaf(ad, st[e], kb * vs[e0 + e]);
    }
    float* op = part + (((size_t)bh * STCH + c) * DH_ + d) * DH_ + e0;
    #pragma unroll
    for (int e = 0; e < 64; e++) op[e] = st[e];
}

__global__ __launch_bounds__(256) void state_comb(const float* __restrict__ part,
                                                  const float* __restrict__ alpha_log,
                                                  float* __restrict__ stout) {
    int bh = blockIdx.x;
    int h = bh & 7;
    int tid = threadIdx.x;
    int d = tid >> 1;
    int e0 = (tid & 1) * 64;
    float ad = sigmoidf_(alpha_log[h * DH_ + d]);
    float a32 = ad;
    a32 *= a32; a32 *= a32; a32 *= a32; a32 *= a32; a32 *= a32;
    const float* p0 = part + (((size_t)bh * STCH + 0) * DH_ + d) * DH_ + e0;
    const float* p1 = part + (((size_t)bh * STCH + 1) * DH_ + d) * DH_ + e0;
    const float* p2 = part + (((size_t)bh * STCH + 2) * DH_ + d) * DH_ + e0;
    const float* p3 = part + (((size_t)bh * STCH + 3) * DH_ + d) * DH_ + e0;
    float* op = stout + ((size_t)bh * DH_ + d) * DH_ + e0;
    #pragma unroll
    for (int e = 0; e < 64; e++) {
        float r = p0[e];
        r = fmaf(r, a32, p1[e]);
        r = fmaf(r, a32, p2[e]);
        r = fmaf(r, a32, p3[e]);
        op[e] = r;
    }
}

// ---------------- launch ----------------
extern "C" void kernel_launch(void* const* d_in, const int* in_sizes, int n_in,
                              void* d_out, int out_size) {
    const float* x         = (const float*)d_in[0];
    const float* Wq        = (const float*)d_in[1];
    const float* Wk        = (const float*)d_in[2];
    const float* Wv        = (const float*)d_in[3];
    const float* Wo        = (const float*)d_in[4];
    const float* Wb        = (const float*)d_in[5];
    const float* bb        = (const float*)d_in[6];
    const float* alpha_log = (const float*)d_in[7];
    float* out = (float*)d_out;

    float *q, *k, *v, *beta, *stpart, *ctab, *stab;
    cudaGetSymbolAddress((void**)&q,      g_q);
    cudaGetSymbolAddress((void**)&k,      g_k);
    cudaGetSymbolAddress((void**)&v,      g_v);
    cudaGetSymbolAddress((void**)&beta,   g_beta);
    cudaGetSymbolAddress((void**)&stpart, g_stpart);
    cudaGetSymbolAddress((void**)&ctab,   g_ctab);
    cudaGetSymbolAddress((void**)&stab,   g_stab);
    __half *xh, *wqh, *wkh, *wvh, *woh, *ah;
    cudaGetSymbolAddress((void**)&xh,  g_xh);
    cudaGetSymbolAddress((void**)&wqh, g_wqh);
    cudaGetSymbolAddress((void**)&wkh, g_wkh);
    cudaGetSymbolAddress((void**)&wvh, g_wvh);
    cudaGetSymbolAddress((void**)&woh, g_woh);
    cudaGetSymbolAddress((void**)&ah,  g_ah);

    cudaFuncSetAttribute(hmma_gemm, cudaFuncAttributeMaxDynamicSharedMemorySize, GEMM_SMEM);

    ropetab_kernel<<<(S_ * 64) / 256, 256>>>(ctab, stab);
    amean_kernel<<<1, 256>>>(alpha_log);

    xprep_kernel<<<MROWS, 256>>>(x, Wb, bb, xh, beta);
    dim3 gcvt((INNER_*DM_/4 + 255)/256, 4);
    cvt4_kernel<<<gcvt, 256>>>(Wq, Wk, Wv, Wo, wqh, wkh, wvh, woh, INNER_*DM_/4);

    // QKV: fused 3-way GEMM, M=4096, N=1024, K=2048
    dim3 gqkv(INNER_/128, MROWS/128, 3);
    hmma_gemm<<<gqkv, 256, GEMM_SMEM>>>(xh, wqh, wkh, wvh,
                                        q, k, v, DM_, INNER_);

    dim3 gattn(S_/ATT_S, H_, B_);
    attn_kernel<<<gattn, 256>>>(q, k, v, beta, ctab, stab, ah);

    // O-proj: M=4096, N=2048, K=1024
    dim3 gout(DM_/128, MROWS/128, 1);
    hmma_gemm<<<gout, 256, GEMM_SMEM>>>(ah, woh, woh, woh,
                                        out, out, out, INNER_, DM_);

    state_part<<<B_ * H_ * STCH, 256>>>(k, v, beta, alpha_log, ctab, stab, stpart);
    state_comb<<<B_ * H_, 256>>>(stpart, alpha_log, out + (size_t)MROWS * DM_);
}

// round 12
// speedup vs baseline: 1.5614x; 1.1055x over previous
#include <cuda_runtime.h>
#include <cuda_fp16.h>
#include <math.h>
#include <stdint.h>

#define B_ 2
#define S_ 2048
#define DM_ 2048
#define H_ 8
#define DH_ 128
#define INNER_ 1024
#define MROWS (B_*S_)   // 4096
#define SROWS S_        // rows per batch

// ---------------- scratch (device globals; no allocation allowed) ----------
__device__ float g_q[MROWS * INNER_];
__device__ float g_k[MROWS * INNER_];
__device__ float g_v[MROWS * INNER_];
__device__ float g_beta[MROWS * H_];
__device__ float g_amean[H_];
__device__ float g_ctab[S_ * 64];
__device__ float g_stab[S_ * 64];

__device__ __align__(128) __half g_xh[MROWS * DM_];
__device__ __align__(128) __half g_wqh[INNER_ * DM_];
__device__ __align__(128) __half g_wkh[INNER_ * DM_];
__device__ __align__(128) __half g_wvh[INNER_ * DM_];
__device__ __align__(128) __half g_woh[DM_ * INNER_];
__device__ __align__(128) __half g_ah[MROWS * INNER_];

#define STWIN_ 128
#define STCH 4
#define STLEN (STWIN_/STCH)   // 32
__device__ float g_stpart[B_ * H_ * STCH * DH_ * DH_];

__device__ __forceinline__ float sigmoidf_(float x) {
    return 1.0f / (1.0f + expf(-x));
}

// ======================= PTX helpers ==============================
__device__ __forceinline__ uint32_t smem_u32(const void* p) {
    uint32_t a;
    asm("{ .reg .u64 t; cvta.to.shared.u64 t, %1; cvt.u32.u64 %0, t; }"
        : "=r"(a) : "l"(p));
    return a;
}

#define CP_ASYNC16(dst, src) \
    asm volatile("cp.async.cg.shared.global [%0], [%1], 16;" :: "r"(dst), "l"(src) : "memory")
#define CP_COMMIT() asm volatile("cp.async.commit_group;" ::: "memory")
#define CP_WAIT(n)  asm volatile("cp.async.wait_group %0;" :: "n"(n) : "memory")

__device__ __forceinline__ void ldsm_x4(uint32_t& r0, uint32_t& r1, uint32_t& r2, uint32_t& r3,
                                        uint32_t addr) {
    asm volatile("ldmatrix.sync.aligned.m8n8.x4.shared.b16 {%0,%1,%2,%3}, [%4];"
        : "=r"(r0), "=r"(r1), "=r"(r2), "=r"(r3) : "r"(addr));
}

__device__ __forceinline__ void mma16816(float* c, const uint32_t* a, uint32_t b0, uint32_t b1) {
    asm volatile(
        "mma.sync.aligned.m16n8k16.row.col.f32.f16.f16.f32 "
        "{%0,%1,%2,%3}, {%4,%5,%6,%7}, {%8,%9}, {%0,%1,%2,%3};"
        : "+f"(c[0]), "+f"(c[1]), "+f"(c[2]), "+f"(c[3])
        : "r"(a[0]), "r"(a[1]), "r"(a[2]), "r"(a[3]), "r"(b0), "r"(b1));
}

// ======================= fused prep kernel ==================================
// blocks [0, MROWS): xprep (x->fp16 + beta)
// blocks [MROWS, MROWS+8192): weight fp32->fp16 (4 weights x 2048 blocks)
// blocks [MROWS+8192, MROWS+8192+512): rope table
// block  MROWS+8192+512: amean
#define PREP_XP   MROWS
#define PREP_CVT  (PREP_XP + 8192)
#define PREP_ROPE (PREP_CVT + 512)
#define PREP_GRID (PREP_ROPE + 1)

__global__ __launch_bounds__(256) void prep_all(
    const float* __restrict__ x,
    const float* __restrict__ Wq, const float* __restrict__ Wk,
    const float* __restrict__ Wv, const float* __restrict__ Wo,
    const float* __restrict__ Wb, const float* __restrict__ bb,
    const float* __restrict__ alpha_log,
    __half* __restrict__ xh,
    __half* __restrict__ wqh, __half* __restrict__ wkh,
    __half* __restrict__ wvh, __half* __restrict__ woh,
    float* __restrict__ beta,
    float* __restrict__ ctab, float* __restrict__ stab) {
    int blk = blockIdx.x;
    int tid = threadIdx.x;
    if (blk < PREP_XP) {
        // ---- xprep ----
        __shared__ float xs[DM_];
        int row = blk;
        const float4* src = (const float4*)(x + (size_t)row * DM_);
        __half2* dst = (__half2*)(xh + (size_t)row * DM_);
        for (int i = tid; i < DM_/4; i += 256) {
            float4 v = src[i];
            *(float4*)&xs[i*4] = v;
            dst[2*i]   = __half2(__float2half(v.x), __float2half(v.y));
            dst[2*i+1] = __half2(__float2half(v.z), __float2half(v.w));
        }
        __syncthreads();
        int w = tid >> 5;
        int lane = tid & 31;
        const float* wr = Wb + w * DM_;
        float sum = 0.f;
        for (int i = lane; i < DM_; i += 32)
            sum += xs[i] * wr[i];
        #pragma unroll
        for (int o = 16; o; o >>= 1) sum += __shfl_xor_sync(0xffffffffu, sum, o);
        if (lane == 0) beta[row * H_ + w] = sigmoidf_(sum + bb[w]);
    } else if (blk < PREP_CVT) {
        // ---- weight conversion ----
        int idx = blk - PREP_XP;
        int seg = idx >> 11;             // 2048 blocks per weight
        const float* s = (seg == 0) ? Wq : (seg == 1) ? Wk : (seg == 2) ? Wv : Wo;
        __half* d = (seg == 0) ? wqh : (seg == 1) ? wkh : (seg == 2) ? wvh : woh;
        int i = (idx & 2047) * 256 + tid;   // < 524288 = INNER_*DM_/4
        float4 v = ((const float4*)s)[i];
        __half2* p = (__half2*)d;
        p[2*i]   = __half2(__float2half(v.x), __float2half(v.y));
        p[2*i+1] = __half2(__float2half(v.z), __float2half(v.w));
    } else if (blk < PREP_ROPE) {
        // ---- rope table ----
        int idx = (blk - PREP_CVT) * 256 + tid;   // < S_*64
        int j = idx & 63;
        int s = idx >> 6;
        float ex = (float)(2 * j) * (1.0f / (float)DH_);
        float inv = powf(10000.0f, -ex);
        float sn, c;
        sincosf((float)s * inv, &sn, &c);
        ctab[idx] = c;
        stab[idx] = sn;
    } else {
        // ---- amean ----
        int w = tid >> 5;
        int lane = tid & 31;
        float s = 0.f;
        for (int d = lane; d < DH_; d += 32)
            s += sigmoidf_(alpha_log[w * DH_ + d]);
        #pragma unroll
        for (int o = 16; o; o >>= 1) s += __shfl_xor_sync(0xffffffffu, s, o);
        if (lane == 0) g_amean[w] = s / (float)DH_;
    }
}

// ======================= fp16 1-pass HMMA GEMM ==============================
// C[M,N](fp32) = Ah[M,K] @ Bh[N,K]^T over rows [m_base, m_base+2048).
// 128x128 CTA tile, k-chunk 64 halves, 3-stage cp.async, single sync, 2 CTAs/SM.
#define NSTG 3
#define TILE_B 16384u
#define STG_BYTES (2u * TILE_B)       // Ah | Bh = 32KB
#define GEMM_SMEM (NSTG * STG_BYTES)  // 96KB

__global__ __launch_bounds__(256, 2) void hmma_gemm(
    const __half* __restrict__ Ah,
    const __half* __restrict__ B0, const __half* __restrict__ B1,
    const __half* __restrict__ B2,
    float* __restrict__ C0, float* __restrict__ C1, float* __restrict__ C2,
    int K, int ldc, int m_base) {
    extern __shared__ char smem[];
    uint32_t sm = smem_u32(smem);
    int tid = threadIdx.x;
    int lane = tid & 31;
    int wid = tid >> 5;
    int wm = wid & 1;
    int wn = wid >> 1;
    int m0 = m_base + blockIdx.y * 128;
    int n0 = blockIdx.x * 128;

    const __half* Bh;
    float* C;
    if (blockIdx.z == 0)      { Bh = B0; C = C0; }
    else if (blockIdx.z == 1) { Bh = B1; C = C1; }
    else                      { Bh = B2; C = C2; }

    int kiters = K >> 6;

    float acc[4][4][4];
    #pragma unroll
    for (int i = 0; i < 4; i++)
        #pragma unroll
        for (int j = 0; j < 4; j++)
            #pragma unroll
            for (int t = 0; t < 4; t++) acc[i][j][t] = 0.f;

    int lc = tid & 7;
    int lr = tid >> 3;

    #define ISSUE_STAGE(ip, buf) do {                                          \
        int _k0 = (ip) << 6;                                                   \
        const __half* _ah = Ah + (size_t)(m0 + lr) * K + _k0 + lc * 8;         \
        const __half* _bh = Bh + (size_t)(n0 + lr) * K + _k0 + lc * 8;         \
        uint32_t _sb = sm + (buf) * STG_BYTES;                                 \
        _Pragma("unroll")                                                      \
        for (int _i = 0; _i < 4; _i++) {                                       \
            int _row = lr + 32 * _i;                                           \
            uint32_t _sw = ((uint32_t)_row << 7) + (((uint32_t)(lc ^ (_row & 7))) << 4); \
            size_t _go = (size_t)(32 * _i) * K;                                \
            CP_ASYNC16(_sb + _sw,          _ah + _go);                         \
            CP_ASYNC16(_sb + TILE_B + _sw, _bh + _go);                         \
        }                                                                      \
    } while (0)

    ISSUE_STAGE(0, 0); CP_COMMIT();
    ISSUE_STAGE(1, 1); CP_COMMIT();

    for (int it = 0; it < kiters; ++it) {
        if (it + 1 < kiters) { CP_WAIT(1); } else { CP_WAIT(0); }
        __syncthreads();
        if (it + 2 < kiters) {
            int nb = it + 2; while (nb >= 3) nb -= 3;
            ISSUE_STAGE(it + 2, nb);
            CP_COMMIT();
        }
        int cb = it; while (cb >= 3) cb -= 3;
        uint32_t sah = sm + cb * STG_BYTES;
        uint32_t sbh = sah + TILE_B;
        #pragma unroll
        for (int ks = 0; ks < 4; ++ks) {
            int ch = ks * 2 + (lane >> 4);
            uint32_t bfr[2][4];
            #pragma unroll
            for (int nt2 = 0; nt2 < 2; ++nt2) {
                int rowB = wn * 32 + nt2 * 16 + (lane & 7) + ((lane >> 3) & 1) * 8;
                uint32_t off = ((uint32_t)rowB << 7) + (((uint32_t)(ch ^ (rowB & 7))) << 4);
                ldsm_x4(bfr[nt2][0], bfr[nt2][1], bfr[nt2][2], bfr[nt2][3], sbh + off);
            }
            #pragma unroll
            for (int mt = 0; mt < 4; ++mt) {
                int rowA = wm * 64 + mt * 16 + (lane & 7) + ((lane >> 3) & 1) * 8;
                uint32_t off = ((uint32_t)rowA << 7) + (((uint32_t)(ch ^ (rowA & 7))) << 4);
                uint32_t a[4];
                ldsm_x4(a[0], a[1], a[2], a[3], sah + off);
                #pragma unroll
                for (int nt2 = 0; nt2 < 2; ++nt2) {
                    mma16816(acc[mt][nt2 * 2 + 0], a, bfr[nt2][0], bfr[nt2][2]);
                    mma16816(acc[mt][nt2 * 2 + 1], a, bfr[nt2][1], bfr[nt2][3]);
                }
            }
        }
    }
    #undef ISSUE_STAGE

    // -------- epilogue --------
    #pragma unroll
    for (int mt = 0; mt < 4; ++mt) {
        int m = m0 + wm * 64 + mt * 16 + (lane >> 2);
        #pragma unroll
        for (int nt = 0; nt < 4; ++nt) {
            int n = n0 + wn * 32 + nt * 8 + (lane & 3) * 2;
            float* p = C + (size_t)m * ldc + n;
            *(float2*)p = make_float2(acc[mt][nt][0], acc[mt][nt][1]);
            *(float2*)(p + 8 * (size_t)ldc) = make_float2(acc[mt][nt][2], acc[mt][nt][3]);
        }
    }
}

// ---------------- smem-tiled windowed decay attention with fused RoPE ------
#define WIN_ 32
#define ATT_S 8
#define ATT_ROWS (WIN_ - 1 + ATT_S)   // 39
__global__ __launch_bounds__(256) void attn_kernel(const float* __restrict__ q,
                                                   const float* __restrict__ k,
                                                   const float* __restrict__ v,
                                                   const float* __restrict__ beta,
                                                   const float* __restrict__ ctab,
                                                   const float* __restrict__ stab,
                                                   __half* __restrict__ ah,
                                                   int b) {
    __shared__ float ks[ATT_ROWS * DH_];
    __shared__ float vs[ATT_ROWS * DH_];
    __shared__ float bs[ATT_ROWS];
    int tid = threadIdx.x;
    int wid = tid >> 5;
    int lane = tid & 31;
    int s0 = blockIdx.x * ATT_S;
    int h  = blockIdx.y;
    int base_t = s0 - (WIN_ - 1);

    size_t bh = (size_t)b * S_ * INNER_ + h * DH_;

    for (int i = tid; i < ATT_ROWS * 32; i += 256) {
        int r = i >> 5;
        int c = (i & 31) * 4;
        int t = base_t + r;
        float4 z = make_float4(0.f, 0.f, 0.f, 0.f);
        float4 kv = z, vv = z;
        if (t >= 0) {
            kv = *(const float4*)(k + bh + (size_t)t * INNER_ + c);
            vv = *(const float4*)(v + bh + (size_t)t * INNER_ + c);
        }
        *(float4*)&ks[r * DH_ + c] = kv;
        *(float4*)&vs[r * DH_ + c] = vv;
    }
    if (tid < ATT_ROWS) {
        int t = base_t + tid;
        bs[tid] = (t >= 0) ? beta[(size_t)(b * S_ + t) * H_ + h] : 0.f;
    }
    __syncthreads();

    for (int i = tid; i < ATT_ROWS * 16; i += 256) {
        int r = i >> 4;
        int c = (i & 15) * 4;
        int t = base_t + r;
        if (t < 0) continue;
        float4 a = *(float4*)&ks[r * DH_ + c];
        float4 p = *(float4*)&ks[r * DH_ + c + 64];
        float4 ct4 = *(const float4*)&ctab[(size_t)t * 64 + c];
        float4 st4 = *(const float4*)&stab[(size_t)t * 64 + c];
        float4 lo, hi;
        lo.x = a.x*ct4.x - p.x*st4.x;  hi.x = p.x*ct4.x + a.x*st4.x;
        lo.y = a.y*ct4.y - p.y*st4.y;  hi.y = p.y*ct4.y + a.y*st4.y;
        lo.z = a.z*ct4.z - p.z*st4.z;  hi.z = p.z*ct4.z + a.z*st4.z;
        lo.w = a.w*ct4.w - p.w*st4.w;  hi.w = p.w*ct4.w + a.w*st4.w;
        *(float4*)&ks[r * DH_ + c]      = lo;
        *(float4*)&ks[r * DH_ + c + 64] = hi;
    }
    __syncthreads();

    int s = s0 + wid;
    float am = g_amean[h];
    float am2 = am * am;
    float am3 = am2 * am;
    float am4 = am2 * am2;
    int c4 = lane * 4;

    float4 qraw = *(const float4*)(q + bh + (size_t)s * INNER_ + c4);
    int jj = (lane & 15) * 4;
    float4 ct4 = *(const float4*)&ctab[(size_t)s * 64 + jj];
    float4 st4 = *(const float4*)&stab[(size_t)s * 64 + jj];
    float px = __shfl_xor_sync(0xffffffffu, qraw.x, 16);
    float py = __shfl_xor_sync(0xffffffffu, qraw.y, 16);
    float pz = __shfl_xor_sync(0xffffffffu, qraw.z, 16);
    float pw = __shfl_xor_sync(0xffffffffu, qraw.w, 16);
    float4 qv;
    if (lane < 16) {
        qv.x = qraw.x*ct4.x - px*st4.x;
        qv.y = qraw.y*ct4.y - py*st4.y;
        qv.z = qraw.z*ct4.z - pz*st4.z;
        qv.w = qraw.w*ct4.w - pw*st4.w;
    } else {
        qv.x = qraw.x*ct4.x + px*st4.x;
        qv.y = qraw.y*ct4.y + py*st4.y;
        qv.z = qraw.z*ct4.z + pz*st4.z;
        qv.w = qraw.w*ct4.w + pw*st4.w;
    }

    float4 acc = make_float4(0.f, 0.f, 0.f, 0.f);
    float decay = 1.f;
    int t_lo = s - (WIN_ - 1); if (t_lo < 0) t_lo = 0;

    for (int t4 = s; t4 >= t_lo; t4 -= 4) {
        int r0 = t4 - base_t;
        bool m1 = t4 - 1 >= t_lo, m2 = t4 - 2 >= t_lo, m3 = t4 - 3 >= t_lo;
        float4 z = make_float4(0.f, 0.f, 0.f, 0.f);
        float4 k0 = *(const float4*)&ks[r0 * DH_ + c4];
        float4 v0 = *(const float4*)&vs[r0 * DH_ + c4];
        float4 k1 = m1 ? *(const float4*)&ks[(r0-1) * DH_ + c4] : z;
        float4 v1 = m1 ? *(const float4*)&vs[(r0-1) * DH_ + c4] : z;
        float4 k2 = m2 ? *(const float4*)&ks[(r0-2) * DH_ + c4] : z;
        float4 v2 = m2 ? *(const float4*)&vs[(r0-2) * DH_ + c4] : z;
        float4 k3 = m3 ? *(const float4*)&ks[(r0-3) * DH_ + c4] : z;
        float4 v3 = m3 ? *(const float4*)&vs[(r0-3) * DH_ + c4] : z;
        float d0 = qv.x*k0.x + qv.y*k0.y + qv.z*k0.z + qv.w*k0.w;
        float d1 = qv.x*k1.x + qv.y*k1.y + qv.z*k1.z + qv.w*k1.w;
        float d2 = qv.x*k2.x + qv.y*k2.y + qv.z*k2.z + qv.w*k2.w;
        float d3 = qv.x*k3.x + qv.y*k3.y + qv.z*k3.z + qv.w*k3.w;
        #pragma unroll
        for (int o = 16; o; o >>= 1) {
            d0 += __shfl_xor_sync(0xffffffffu, d0, o);
            d1 += __shfl_xor_sync(0xffffffffu, d1, o);
            d2 += __shfl_xor_sync(0xffffffffu, d2, o);
            d3 += __shfl_xor_sync(0xffffffffu, d3, o);
        }
        float w0 = d0 * decay * bs[r0];
        float w1 = m1 ? d1 * decay * am  * bs[r0-1] : 0.f;
        float w2 = m2 ? d2 * decay * am2 * bs[r0-2] : 0.f;
        float w3 = m3 ? d3 * decay * am3 * bs[r0-3] : 0.f;
        acc.x = fmaf(w0, v0.x, fmaf(w1, v1.x, fmaf(w2, v2.x, fmaf(w3, v3.x, acc.x))));
        acc.y = fmaf(w0, v0.y, fmaf(w1, v1.y, fmaf(w2, v2.y, fmaf(w3, v3.y, acc.y))));
        acc.z = fmaf(w0, v0.z, fmaf(w1, v1.z, fmaf(w2, v2.z, fmaf(w3, v3.z, acc.z))));
        acc.w = fmaf(w0, v0.w, fmaf(w1, v1.w, fmaf(w2, v2.w, fmaf(w3, v3.w, acc.w))));
        decay *= am4;
    }
    size_t o = bh + (size_t)s * INNER_ + c4;
    ((__half2*)(ah + o))[0] = __half2(__float2half(acc.x), __float2half(acc.y));
    ((__half2*)(ah + o))[1] = __half2(__float2half(acc.z), __float2half(acc.w));
}

// ---------------- recurrent state: partial chunks + combine ----------------
__global__ __launch_bounds__(256) void state_part(const float* __restrict__ k,
                                                  const float* __restrict__ v,
                                                  const float* __restrict__ beta,
                                                  const float* __restrict__ alpha_log,
                                                  const float* __restrict__ ctab,
                                                  const float* __restrict__ stab,
                                                  float* __restrict__ part,
                                                  int b) {
    int h  = blockIdx.x >> 2;        // 0..7
    int c  = blockIdx.x & 3;
    int bh = b * H_ + h;
    int tid = threadIdx.x;
    int d = tid >> 1;
    int e0 = (tid & 1) * 64;
    __shared__ float ks[DH_], vs[DH_];
    float st[64];
    #pragma unroll
    for (int e = 0; e < 64; e++) st[e] = 0.f;
    float ad = sigmoidf_(alpha_log[h * DH_ + d]);
    int tbeg = S_ - STWIN_ + c * STLEN;
    for (int t = tbeg; t < tbeg + STLEN; t++) {
        __syncthreads();
        size_t base = (size_t)(b * S_ + t) * INNER_ + h * DH_;
        if (tid < 128) ks[tid] = k[base + tid];
        else           vs[tid - 128] = v[base + tid - 128];
        __syncthreads();
        float cv = ctab[(size_t)t * 64 + (d & 63)];
        float sv = stab[(size_t)t * 64 + (d & 63)];
        float kd = (d < 64) ? ks[d] * cv - ks[d + 64] * sv
                            : ks[d] * cv + ks[d - 64] * sv;
        float kb = kd * beta[(b * S_ + t) * H_ + h];
        #pragma unroll
        for (int e = 0; e < 64; e++)
            st[e] = fmaf(ad, st[e], kb * vs[e0 + e]);
    }
    float* op = part + (((size_t)bh * STCH + c) * DH_ + d) * DH_ + e0;
    #pragma unroll
    for (int e = 0; e < 64; e++) op[e] = st[e];
}

__global__ __launch_bounds__(256) void state_comb(const float* __restrict__ part,
                                                  const float* __restrict__ alpha_log,
                                                  float* __restrict__ stout) {
    int bh = blockIdx.x;
    int h = bh & 7;
    int tid = threadIdx.x;
    int d = tid >> 1;
    int e0 = (tid & 1) * 64;
    float ad = sigmoidf_(alpha_log[h * DH_ + d]);
    float a32 = ad;
    a32 *= a32; a32 *= a32; a32 *= a32; a32 *= a32; a32 *= a32;
    const float* p0 = part + (((size_t)bh * STCH + 0) * DH_ + d) * DH_ + e0;
    const float* p1 = part + (((size_t)bh * STCH + 1) * DH_ + d) * DH_ + e0;
    const float* p2 = part + (((size_t)bh * STCH + 2) * DH_ + d) * DH_ + e0;
    const float* p3 = part + (((size_t)bh * STCH + 3) * DH_ + d) * DH_ + e0;
    float* op = stout + ((size_t)bh * DH_ + d) * DH_ + e0;
    #pragma unroll
    for (int e = 0; e < 64; e++) {
        float r = p0[e];
        r = fmaf(r, a32, p1[e]);
        r = fmaf(r, a32, p2[e]);
        r = fmaf(r, a32, p3[e]);
        op[e] = r;
    }
}

// ---------------- launch ----------------
extern "C" void kernel_launch(void* const* d_in, const int* in_sizes, int n_in,
                              void* d_out, int out_size) {
    const float* x         = (const float*)d_in[0];
    const float* Wq        = (const float*)d_in[1];
    const float* Wk        = (const float*)d_in[2];
    const float* Wv        = (const float*)d_in[3];
    const float* Wo        = (const float*)d_in[4];
    const float* Wb        = (const float*)d_in[5];
    const float* bb        = (const float*)d_in[6];
    const float* alpha_log = (const float*)d_in[7];
    float* out = (float*)d_out;

    float *q, *k, *v, *beta, *stpart, *ctab, *stab;
    cudaGetSymbolAddress((void**)&q,      g_q);
    cudaGetSymbolAddress((void**)&k,      g_k);
    cudaGetSymbolAddress((void**)&v,      g_v);
    cudaGetSymbolAddress((void**)&beta,   g_beta);
    cudaGetSymbolAddress((void**)&stpart, g_stpart);
    cudaGetSymbolAddress((void**)&ctab,   g_ctab);
    cudaGetSymbolAddress((void**)&stab,   g_stab);
    __half *xh, *wqh, *wkh, *wvh, *woh, *ah;
    cudaGetSymbolAddress((void**)&xh,  g_xh);
    cudaGetSymbolAddress((void**)&wqh, g_wqh);
    cudaGetSymbolAddress((void**)&wkh, g_wkh);
    cudaGetSymbolAddress((void**)&wvh, g_wvh);
    cudaGetSymbolAddress((void**)&woh, g_woh);
    cudaGetSymbolAddress((void**)&ah,  g_ah);

    // one-time resources (host-side handles, no device memory)
    static cudaStream_t s1 = 0;
    static cudaEvent_t eQ0, eQ1, eA0, eA1, eS;
    if (!s1) {
        cudaStreamCreateWithFlags(&s1, cudaStreamNonBlocking);
        cudaEventCreateWithFlags(&eQ0, cudaEventDisableTiming);
        cudaEventCreateWithFlags(&eQ1, cudaEventDisableTiming);
        cudaEventCreateWithFlags(&eA0, cudaEventDisableTiming);
        cudaEventCreateWithFlags(&eA1, cudaEventDisableTiming);
        cudaEventCreateWithFlags(&eS,  cudaEventDisableTiming);
        cudaFuncSetAttribute(hmma_gemm, cudaFuncAttributeMaxDynamicSharedMemorySize, GEMM_SMEM);
    }

    // ---- prep (everything independent, one launch) ----
    prep_all<<<PREP_GRID, 256>>>(x, Wq, Wk, Wv, Wo, Wb, bb, alpha_log,
                                 xh, wqh, wkh, wvh, woh, beta, ctab, stab);

    // ---- QKV GEMMs, split by batch ----
    dim3 gqkv(INNER_/128, SROWS/128, 3);
    hmma_gemm<<<gqkv, 256, GEMM_SMEM>>>(xh, wqh, wkh, wvh, q, k, v, DM_, INNER_, 0);
    cudaEventRecord(eQ0, 0);
    hmma_gemm<<<gqkv, 256, GEMM_SMEM>>>(xh, wqh, wkh, wvh, q, k, v, DM_, INNER_, SROWS);
    cudaEventRecord(eQ1, 0);

    // ---- side stream: attention + state, per batch ----
    dim3 gattn(S_/ATT_S, H_, 1);
    cudaStreamWaitEvent(s1, eQ0, 0);
    attn_kernel<<<gattn, 256, 0, s1>>>(q, k, v, beta, ctab, stab, ah, 0);
    cudaEventRecord(eA0, s1);
    state_part<<<H_ * STCH, 256, 0, s1>>>(k, v, beta, alpha_log, ctab, stab, stpart, 0);
    cudaStreamWaitEvent(s1, eQ1, 0);
    attn_kernel<<<gattn, 256, 0, s1>>>(q, k, v, beta, ctab, stab, ah, 1);
    cudaEventRecord(eA1, s1);
    state_part<<<H_ * STCH, 256, 0, s1>>>(k, v, beta, alpha_log, ctab, stab, stpart, 1);
    state_comb<<<B_ * H_, 256, 0, s1>>>(stpart, alpha_log, out + (size_t)MROWS * DM_);
    cudaEventRecord(eS, s1);

    // ---- O-proj GEMMs on main stream, per batch ----
    dim3 gout(DM_/128, SROWS/128, 1);
    cudaStreamWaitEvent(0, eA0, 0);
    hmma_gemm<<<gout, 256, GEMM_SMEM>>>(ah, woh, woh, woh, out, out, out, INNER_, DM_, 0);
    cudaStreamWaitEvent(0, eA1, 0);
    hmma_gemm<<<gout, 256, GEMM_SMEM>>>(ah, woh, woh, woh, out, out, out, INNER_, DM_, SROWS);

    // ---- join side stream back ----
    cudaStreamWaitEvent(0, eS, 0);
}

// round 13
// speedup vs baseline: 1.5733x; 1.0076x over previous
#include <cuda_runtime.h>
#include <cuda_fp16.h>
#include <math.h>
#include <stdint.h>

#define B_ 2
#define S_ 2048
#define DM_ 2048
#define H_ 8
#define DH_ 128
#define INNER_ 1024
#define MROWS (B_*S_)   // 4096
#define SROWS S_        // rows per batch
#define HROWS (S_/2)    // rows per half-batch chunk

// ---------------- scratch (device globals; no allocation allowed) ----------
__device__ float g_q[MROWS * INNER_];
__device__ float g_k[MROWS * INNER_];
__device__ float g_v[MROWS * INNER_];
__device__ float g_beta[MROWS * H_];
__device__ float g_amean[H_];
__device__ float g_ctab[S_ * 64];
__device__ float g_stab[S_ * 64];

__device__ __align__(128) __half g_xh[MROWS * DM_];
__device__ __align__(128) __half g_wqh[INNER_ * DM_];
__device__ __align__(128) __half g_wkh[INNER_ * DM_];
__device__ __align__(128) __half g_wvh[INNER_ * DM_];
__device__ __align__(128) __half g_woh[DM_ * INNER_];
__device__ __align__(128) __half g_ah[MROWS * INNER_];

#define STWIN_ 128
#define STCH 4
#define STLEN (STWIN_/STCH)   // 32
__device__ float g_stpart[B_ * H_ * STCH * DH_ * DH_];

__device__ __forceinline__ float sigmoidf_(float x) {
    return 1.0f / (1.0f + expf(-x));
}

// ======================= PTX helpers ==============================
__device__ __forceinline__ uint32_t smem_u32(const void* p) {
    uint32_t a;
    asm("{ .reg .u64 t; cvta.to.shared.u64 t, %1; cvt.u32.u64 %0, t; }"
        : "=r"(a) : "l"(p));
    return a;
}

#define CP_ASYNC16(dst, src) \
    asm volatile("cp.async.cg.shared.global [%0], [%1], 16;" :: "r"(dst), "l"(src) : "memory")
#define CP_COMMIT() asm volatile("cp.async.commit_group;" ::: "memory")
#define CP_WAIT(n)  asm volatile("cp.async.wait_group %0;" :: "n"(n) : "memory")

__device__ __forceinline__ void ldsm_x4(uint32_t& r0, uint32_t& r1, uint32_t& r2, uint32_t& r3,
                                        uint32_t addr) {
    asm volatile("ldmatrix.sync.aligned.m8n8.x4.shared.b16 {%0,%1,%2,%3}, [%4];"
        : "=r"(r0), "=r"(r1), "=r"(r2), "=r"(r3) : "r"(addr));
}

__device__ __forceinline__ void mma16816(float* c, const uint32_t* a, uint32_t b0, uint32_t b1) {
    asm volatile(
        "mma.sync.aligned.m16n8k16.row.col.f32.f16.f16.f32 "
        "{%0,%1,%2,%3}, {%4,%5,%6,%7}, {%8,%9}, {%0,%1,%2,%3};"
        : "+f"(c[0]), "+f"(c[1]), "+f"(c[2]), "+f"(c[3])
        : "r"(a[0]), "r"(a[1]), "r"(a[2]), "r"(a[3]), "r"(b0), "r"(b1));
}

// ======================= prep_main: x->fp16 + weight->fp16 ==================
// blocks [0, 8192): x cvt; [8192, 16384): weight cvt (4 x 2048 blocks)
__global__ __launch_bounds__(256) void prep_main(
    const float* __restrict__ x,
    const float* __restrict__ Wq, const float* __restrict__ Wk,
    const float* __restrict__ Wv, const float* __restrict__ Wo,
    __half* __restrict__ xh,
    __half* __restrict__ wqh, __half* __restrict__ wkh,
    __half* __restrict__ wvh, __half* __restrict__ woh) {
    int blk = blockIdx.x;
    int tid = threadIdx.x;
    const float* s;
    __half* d;
    int i;
    if (blk < 8192) {
        s = x; d = xh;
        i = blk * 256 + tid;            // < MROWS*DM_/4 = 2097152
    } else {
        int idx = blk - 8192;
        int seg = idx >> 11;
        s = (seg == 0) ? Wq : (seg == 1) ? Wk : (seg == 2) ? Wv : Wo;
        d = (seg == 0) ? wqh : (seg == 1) ? wkh : (seg == 2) ? wvh : woh;
        i = (idx & 2047) * 256 + tid;   // < INNER_*DM_/4 = 524288
    }
    float4 v = ((const float4*)s)[i];
    __half2* p = (__half2*)d;
    p[2*i]   = __half2(__float2half(v.x), __float2half(v.y));
    p[2*i+1] = __half2(__float2half(v.z), __float2half(v.w));
}

// ======================= prep_side: beta + rope table + amean ===============
// blocks [0, MROWS): beta; [MROWS, MROWS+512): rope; block MROWS+512: amean
#define PS_BETA MROWS
#define PS_ROPE (PS_BETA + 512)
#define PS_GRID (PS_ROPE + 1)
__global__ __launch_bounds__(256) void prep_side(
    const float* __restrict__ x,
    const float* __restrict__ Wb, const float* __restrict__ bb,
    const float* __restrict__ alpha_log,
    float* __restrict__ beta,
    float* __restrict__ ctab, float* __restrict__ stab) {
    int blk = blockIdx.x;
    int tid = threadIdx.x;
    if (blk < PS_BETA) {
        __shared__ float xs[DM_];
        int row = blk;
        const float4* src = (const float4*)(x + (size_t)row * DM_);
        for (int i = tid; i < DM_/4; i += 256)
            *(float4*)&xs[i*4] = src[i];
        __syncthreads();
        int w = tid >> 5;
        int lane = tid & 31;
        const float* wr = Wb + w * DM_;
        float sum = 0.f;
        for (int i = lane; i < DM_; i += 32)
            sum += xs[i] * wr[i];
        #pragma unroll
        for (int o = 16; o; o >>= 1) sum += __shfl_xor_sync(0xffffffffu, sum, o);
        if (lane == 0) beta[row * H_ + w] = sigmoidf_(sum + bb[w]);
    } else if (blk < PS_ROPE) {
        int idx = (blk - PS_BETA) * 256 + tid;   // < S_*64
        int j = idx & 63;
        int s = idx >> 6;
        float ex = (float)(2 * j) * (1.0f / (float)DH_);
        float inv = powf(10000.0f, -ex);
        float sn, c;
        sincosf((float)s * inv, &sn, &c);
        ctab[idx] = c;
        stab[idx] = sn;
    } else {
        int w = tid >> 5;
        int lane = tid & 31;
        float s = 0.f;
        for (int d = lane; d < DH_; d += 32)
            s += sigmoidf_(alpha_log[w * DH_ + d]);
        #pragma unroll
        for (int o = 16; o; o >>= 1) s += __shfl_xor_sync(0xffffffffu, s, o);
        if (lane == 0) g_amean[w] = s / (float)DH_;
    }
}

// ======================= fp16 1-pass HMMA GEMM ==============================
#define NSTG 3
#define TILE_B 16384u
#define STG_BYTES (2u * TILE_B)
#define GEMM_SMEM (NSTG * STG_BYTES)  // 96KB

__global__ __launch_bounds__(256, 2) void hmma_gemm(
    const __half* __restrict__ Ah,
    const __half* __restrict__ B0, const __half* __restrict__ B1,
    const __half* __restrict__ B2,
    float* __restrict__ C0, float* __restrict__ C1, float* __restrict__ C2,
    int K, int ldc, int m_base) {
    extern __shared__ char smem[];
    uint32_t sm = smem_u32(smem);
    int tid = threadIdx.x;
    int lane = tid & 31;
    int wid = tid >> 5;
    int wm = wid & 1;
    int wn = wid >> 1;
    int m0 = m_base + blockIdx.y * 128;
    int n0 = blockIdx.x * 128;

    const __half* Bh;
    float* C;
    if (blockIdx.z == 0)      { Bh = B0; C = C0; }
    else if (blockIdx.z == 1) { Bh = B1; C = C1; }
    else                      { Bh = B2; C = C2; }

    int kiters = K >> 6;

    float acc[4][4][4];
    #pragma unroll
    for (int i = 0; i < 4; i++)
        #pragma unroll
        for (int j = 0; j < 4; j++)
            #pragma unroll
            for (int t = 0; t < 4; t++) acc[i][j][t] = 0.f;

    int lc = tid & 7;
    int lr = tid >> 3;

    #define ISSUE_STAGE(ip, buf) do {                                          \
        int _k0 = (ip) << 6;                                                   \
        const __half* _ah = Ah + (size_t)(m0 + lr) * K + _k0 + lc * 8;         \
        const __half* _bh = Bh + (size_t)(n0 + lr) * K + _k0 + lc * 8;         \
        uint32_t _sb = sm + (buf) * STG_BYTES;                                 \
        _Pragma("unroll")                                                      \
        for (int _i = 0; _i < 4; _i++) {                                       \
            int _row = lr + 32 * _i;                                           \
            uint32_t _sw = ((uint32_t)_row << 7) + (((uint32_t)(lc ^ (_row & 7))) << 4); \
            size_t _go = (size_t)(32 * _i) * K;                                \
            CP_ASYNC16(_sb + _sw,          _ah + _go);                         \
            CP_ASYNC16(_sb + TILE_B + _sw, _bh + _go);                         \
        }                                                                      \
    } while (0)

    ISSUE_STAGE(0, 0); CP_COMMIT();
    ISSUE_STAGE(1, 1); CP_COMMIT();

    for (int it = 0; it < kiters; ++it) {
        if (it + 1 < kiters) { CP_WAIT(1); } else { CP_WAIT(0); }
        __syncthreads();
        if (it + 2 < kiters) {
            int nb = it + 2; while (nb >= 3) nb -= 3;
            ISSUE_STAGE(it + 2, nb);
            CP_COMMIT();
        }
        int cb = it; while (cb >= 3) cb -= 3;
        uint32_t sah = sm + cb * STG_BYTES;
        uint32_t sbh = sah + TILE_B;
        #pragma unroll
        for (int ks = 0; ks < 4; ++ks) {
            int ch = ks * 2 + (lane >> 4);
            uint32_t bfr[2][4];
            #pragma unroll
            for (int nt2 = 0; nt2 < 2; ++nt2) {
                int rowB = wn * 32 + nt2 * 16 + (lane & 7) + ((lane >> 3) & 1) * 8;
                uint32_t off = ((uint32_t)rowB << 7) + (((uint32_t)(ch ^ (rowB & 7))) << 4);
                ldsm_x4(bfr[nt2][0], bfr[nt2][1], bfr[nt2][2], bfr[nt2][3], sbh + off);
            }
            #pragma unroll
            for (int mt = 0; mt < 4; ++mt) {
                int rowA = wm * 64 + mt * 16 + (lane & 7) + ((lane >> 3) & 1) * 8;
                uint32_t off = ((uint32_t)rowA << 7) + (((uint32_t)(ch ^ (rowA & 7))) << 4);
                uint32_t a[4];
                ldsm_x4(a[0], a[1], a[2], a[3], sah + off);
                #pragma unroll
                for (int nt2 = 0; nt2 < 2; ++nt2) {
                    mma16816(acc[mt][nt2 * 2 + 0], a, bfr[nt2][0], bfr[nt2][2]);
                    mma16816(acc[mt][nt2 * 2 + 1], a, bfr[nt2][1], bfr[nt2][3]);
                }
            }
        }
    }
    #undef ISSUE_STAGE

    #pragma unroll
    for (int mt = 0; mt < 4; ++mt) {
        int m = m0 + wm * 64 + mt * 16 + (lane >> 2);
        #pragma unroll
        for (int nt = 0; nt < 4; ++nt) {
            int n = n0 + wn * 32 + nt * 8 + (lane & 3) * 2;
            float* p = C + (size_t)m * ldc + n;
            *(float2*)p = make_float2(acc[mt][nt][0], acc[mt][nt][1]);
            *(float2*)(p + 8 * (size_t)ldc) = make_float2(acc[mt][nt][2], acc[mt][nt][3]);
        }
    }
}

// ---------------- smem-tiled windowed decay attention with fused RoPE ------
#define WIN_ 32
#define ATT_S 8
#define ATT_ROWS (WIN_ - 1 + ATT_S)   // 39
__global__ __launch_bounds__(256) void attn_kernel(const float* __restrict__ q,
                                                   const float* __restrict__ k,
                                                   const float* __restrict__ v,
                                                   const float* __restrict__ beta,
                                                   const float* __restrict__ ctab,
                                                   const float* __restrict__ stab,
                                                   __half* __restrict__ ah,
                                                   int b, int s_base) {
    __shared__ float ks[ATT_ROWS * DH_];
    __shared__ float vs[ATT_ROWS * DH_];
    __shared__ float bs[ATT_ROWS];
    int tid = threadIdx.x;
    int wid = tid >> 5;
    int lane = tid & 31;
    int s0 = s_base + blockIdx.x * ATT_S;
    int h  = blockIdx.y;
    int base_t = s0 - (WIN_ - 1);

    size_t bh = (size_t)b * S_ * INNER_ + h * DH_;

    for (int i = tid; i < ATT_ROWS * 32; i += 256) {
        int r = i >> 5;
        int c = (i & 31) * 4;
        int t = base_t + r;
        float4 z = make_float4(0.f, 0.f, 0.f, 0.f);
        float4 kv = z, vv = z;
        if (t >= 0) {
            kv = *(const float4*)(k + bh + (size_t)t * INNER_ + c);
            vv = *(const float4*)(v + bh + (size_t)t * INNER_ + c);
        }
        *(float4*)&ks[r * DH_ + c] = kv;
        *(float4*)&vs[r * DH_ + c] = vv;
    }
    if (tid < ATT_ROWS) {
        int t = base_t + tid;
        bs[tid] = (t >= 0) ? beta[(size_t)(b * S_ + t) * H_ + h] : 0.f;
    }
    __syncthreads();

    for (int i = tid; i < ATT_ROWS * 16; i += 256) {
        int r = i >> 4;
        int c = (i & 15) * 4;
        int t = base_t + r;
        if (t < 0) continue;
        float4 a = *(float4*)&ks[r * DH_ + c];
        float4 p = *(float4*)&ks[r * DH_ + c + 64];
        float4 ct4 = *(const float4*)&ctab[(size_t)t * 64 + c];
        float4 st4 = *(const float4*)&stab[(size_t)t * 64 + c];
        float4 lo, hi;
        lo.x = a.x*ct4.x - p.x*st4.x;  hi.x = p.x*ct4.x + a.x*st4.x;
        lo.y = a.y*ct4.y - p.y*st4.y;  hi.y = p.y*ct4.y + a.y*st4.y;
        lo.z = a.z*ct4.z - p.z*st4.z;  hi.z = p.z*ct4.z + a.z*st4.z;
        lo.w = a.w*ct4.w - p.w*st4.w;  hi.w = p.w*ct4.w + a.w*st4.w;
        *(float4*)&ks[r * DH_ + c]      = lo;
        *(float4*)&ks[r * DH_ + c + 64] = hi;
    }
    __syncthreads();

    int s = s0 + wid;
    float am = g_amean[h];
    float am2 = am * am;
    float am3 = am2 * am;
    float am4 = am2 * am2;
    int c4 = lane * 4;

    float4 qraw = *(const float4*)(q + bh + (size_t)s * INNER_ + c4);
    int jj = (lane & 15) * 4;
    float4 ct4 = *(const float4*)&ctab[(size_t)s * 64 + jj];
    float4 st4 = *(const float4*)&stab[(size_t)s * 64 + jj];
    float px = __shfl_xor_sync(0xffffffffu, qraw.x, 16);
    float py = __shfl_xor_sync(0xffffffffu, qraw.y, 16);
    float pz = __shfl_xor_sync(0xffffffffu, qraw.z, 16);
    float pw = __shfl_xor_sync(0xffffffffu, qraw.w, 16);
    float4 qv;
    if (lane < 16) {
        qv.x = qraw.x*ct4.x - px*st4.x;
        qv.y = qraw.y*ct4.y - py*st4.y;
        qv.z = qraw.z*ct4.z - pz*st4.z;
        qv.w = qraw.w*ct4.w - pw*st4.w;
    } else {
        qv.x = qraw.x*ct4.x + px*st4.x;
        qv.y = qraw.y*ct4.y + py*st4.y;
        qv.z = qraw.z*ct4.z + pz*st4.z;
        qv.w = qraw.w*ct4.w + pw*st4.w;
    }

    float4 acc = make_float4(0.f, 0.f, 0.f, 0.f);
    float decay = 1.f;
    int t_lo = s - (WIN_ - 1); if (t_lo < 0) t_lo = 0;

    for (int t4 = s; t4 >= t_lo; t4 -= 4) {
        int r0 = t4 - base_t;
        bool m1 = t4 - 1 >= t_lo, m2 = t4 - 2 >= t_lo, m3 = t4 - 3 >= t_lo;
        float4 z = make_float4(0.f, 0.f, 0.f, 0.f);
        float4 k0 = *(const float4*)&ks[r0 * DH_ + c4];
        float4 v0 = *(const float4*)&vs[r0 * DH_ + c4];
        float4 k1 = m1 ? *(const float4*)&ks[(r0-1) * DH_ + c4] : z;
        float4 v1 = m1 ? *(const float4*)&vs[(r0-1) * DH_ + c4] : z;
        float4 k2 = m2 ? *(const float4*)&ks[(r0-2) * DH_ + c4] : z;
        float4 v2 = m2 ? *(const float4*)&vs[(r0-2) * DH_ + c4] : z;
        float4 k3 = m3 ? *(const float4*)&ks[(r0-3) * DH_ + c4] : z;
        float4 v3 = m3 ? *(const float4*)&vs[(r0-3) * DH_ + c4] : z;
        float d0 = qv.x*k0.x + qv.y*k0.y + qv.z*k0.z + qv.w*k0.w;
        float d1 = qv.x*k1.x + qv.y*k1.y + qv.z*k1.z + qv.w*k1.w;
        float d2 = qv.x*k2.x + qv.y*k2.y + qv.z*k2.z + qv.w*k2.w;
        float d3 = qv.x*k3.x + qv.y*k3.y + qv.z*k3.z + qv.w*k3.w;
        #pragma unroll
        for (int o = 16; o; o >>= 1) {
            d0 += __shfl_xor_sync(0xffffffffu, d0, o);
            d1 += __shfl_xor_sync(0xffffffffu, d1, o);
            d2 += __shfl_xor_sync(0xffffffffu, d2, o);
            d3 += __shfl_xor_sync(0xffffffffu, d3, o);
        }
        float w0 = d0 * decay * bs[r0];
        float w1 = m1 ? d1 * decay * am  * bs[r0-1] : 0.f;
        float w2 = m2 ? d2 * decay * am2 * bs[r0-2] : 0.f;
        float w3 = m3 ? d3 * decay * am3 * bs[r0-3] : 0.f;
        acc.x = fmaf(w0, v0.x, fmaf(w1, v1.x, fmaf(w2, v2.x, fmaf(w3, v3.x, acc.x))));
        acc.y = fmaf(w0, v0.y, fmaf(w1, v1.y, fmaf(w2, v2.y, fmaf(w3, v3.y, acc.y))));
        acc.z = fmaf(w0, v0.z, fmaf(w1, v1.z, fmaf(w2, v2.z, fmaf(w3, v3.z, acc.z))));
        acc.w = fmaf(w0, v0.w, fmaf(w1, v1.w, fmaf(w2, v2.w, fmaf(w3, v3.w, acc.w))));
        decay *= am4;
    }
    size_t o = bh + (size_t)s * INNER_ + c4;
    ((__half2*)(ah + o))[0] = __half2(__float2half(acc.x), __float2half(acc.y));
    ((__half2*)(ah + o))[1] = __half2(__float2half(acc.z), __float2half(acc.w));
}

// ---------------- recurrent state: partial chunks + combine ----------------
__global__ __launch_bounds__(256) void state_part(const float* __restrict__ k,
                                                  const float* __restrict__ v,
                                                  const float* __restrict__ beta,
                                                  const float* __restrict__ alpha_log,
                                                  const float* __restrict__ ctab,
                                                  const float* __restrict__ stab,
                                                  float* __restrict__ part,
                                                  int b) {
    int h  = blockIdx.x >> 2;
    int c  = blockIdx.x & 3;
    int bh = b * H_ + h;
    int tid = threadIdx.x;
    int d = tid >> 1;
    int e0 = (tid & 1) * 64;
    __shared__ float ks[DH_], vs[DH_];
    float st[64];
    #pragma unroll
    for (int e = 0; e < 64; e++) st[e] = 0.f;
    float ad = sigmoidf_(alpha_log[h * DH_ + d]);
    int tbeg = S_ - STWIN_ + c * STLEN;
    for (int t = tbeg; t < tbeg + STLEN; t++) {
        __syncthreads();
        size_t base = (size_t)(b * S_ + t) * INNER_ + h * DH_;
        if (tid < 128) ks[tid] = k[base + tid];
        else           vs[tid - 128] = v[base + tid - 128];
        __syncthreads();
        float cv = ctab[(size_t)t * 64 + (d & 63)];
        float sv = stab[(size_t)t * 64 + (d & 63)];
        float kd = (d < 64) ? ks[d] * cv - ks[d + 64] * sv
                            : ks[d] * cv + ks[d - 64] * sv;
        float kb = kd * beta[(b * S_ + t) * H_ + h];
        #pragma unroll
        for (int e = 0; e < 64; e++)
            st[e] = fmaf(ad, st[e], kb * vs[e0 + e]);
    }
    float* op = part + (((size_t)bh * STCH + c) * DH_ + d) * DH_ + e0;
    #pragma unroll
    for (int e = 0; e < 64; e++) op[e] = st[e];
}

__global__ __launch_bounds__(256) void state_comb(const float* __restrict__ part,
                                                  const float* __restrict__ alpha_log,
                                                  float* __restrict__ stout) {
    int bh = blockIdx.x;
    int h = bh & 7;
    int tid = threadIdx.x;
    int d = tid >> 1;
    int e0 = (tid & 1) * 64;
    float ad = sigmoidf_(alpha_log[h * DH_ + d]);
    float a32 = ad;
    a32 *= a32; a32 *= a32; a32 *= a32; a32 *= a32; a32 *= a32;
    const float* p0 = part + (((size_t)bh * STCH + 0) * DH_ + d) * DH_ + e0;
    const float* p1 = part + (((size_t)bh * STCH + 1) * DH_ + d) * DH_ + e0;
    const float* p2 = part + (((size_t)bh * STCH + 2) * DH_ + d) * DH_ + e0;
    const float* p3 = part + (((size_t)bh * STCH + 3) * DH_ + d) * DH_ + e0;
    float* op = stout + ((size_t)bh * DH_ + d) * DH_ + e0;
    #pragma unroll
    for (int e = 0; e < 64; e++) {
        float r = p0[e];
        r = fmaf(r, a32, p1[e]);
        r = fmaf(r, a32, p2[e]);
        r = fmaf(r, a32, p3[e]);
        op[e] = r;
    }
}

// ---------------- launch ----------------
extern "C" void kernel_launch(void* const* d_in, const int* in_sizes, int n_in,
                              void* d_out, int out_size) {
    const float* x         = (const float*)d_in[0];
    const float* Wq        = (const float*)d_in[1];
    const float* Wk        = (const float*)d_in[2];
    const float* Wv        = (const float*)d_in[3];
    const float* Wo        = (const float*)d_in[4];
    const float* Wb        = (const float*)d_in[5];
    const float* bb        = (const float*)d_in[6];
    const float* alpha_log = (const float*)d_in[7];
    float* out = (float*)d_out;

    float *q, *k, *v, *beta, *stpart, *ctab, *stab;
    cudaGetSymbolAddress((void**)&q,      g_q);
    cudaGetSymbolAddress((void**)&k,      g_k);
    cudaGetSymbolAddress((void**)&v,      g_v);
    cudaGetSymbolAddress((void**)&beta,   g_beta);
    cudaGetSymbolAddress((void**)&stpart, g_stpart);
    cudaGetSymbolAddress((void**)&ctab,   g_ctab);
    cudaGetSymbolAddress((void**)&stab,   g_stab);
    __half *xh, *wqh, *wkh, *wvh, *woh, *ah;
    cudaGetSymbolAddress((void**)&xh,  g_xh);
    cudaGetSymbolAddress((void**)&wqh, g_wqh);
    cudaGetSymbolAddress((void**)&wkh, g_wkh);
    cudaGetSymbolAddress((void**)&wvh, g_wvh);
    cudaGetSymbolAddress((void**)&woh, g_woh);
    cudaGetSymbolAddress((void**)&ah,  g_ah);

    // one-time resources (host-side handles, no device memory)
    static cudaStream_t s1 = 0;
    static cudaEvent_t eQ0, eQ1, eA0a, eA0b, eA1a, eA1b, eS;
    if (!s1) {
        cudaStreamCreateWithFlags(&s1, cudaStreamNonBlocking);
        cudaEventCreateWithFlags(&eQ0,  cudaEventDisableTiming);
        cudaEventCreateWithFlags(&eQ1,  cudaEventDisableTiming);
        cudaEventCreateWithFlags(&eA0a, cudaEventDisableTiming);
        cudaEventCreateWithFlags(&eA0b, cudaEventDisableTiming);
        cudaEventCreateWithFlags(&eA1a, cudaEventDisableTiming);
        cudaEventCreateWithFlags(&eA1b, cudaEventDisableTiming);
        cudaEventCreateWithFlags(&eS,   cudaEventDisableTiming);
        cudaFuncSetAttribute(hmma_gemm, cudaFuncAttributeMaxDynamicSharedMemorySize, GEMM_SMEM);
    }

    // ---- prep: main-stream (xh + weights) ∥ side-stream (beta/rope/amean) --
    prep_main<<<16384, 256>>>(x, Wq, Wk, Wv, Wo, xh, wqh, wkh, wvh, woh);
    prep_side<<<PS_GRID, 256, 0, s1>>>(x, Wb, bb, alpha_log, beta, ctab, stab);

    // ---- QKV GEMMs, split by batch ----
    dim3 gqkv(INNER_/128, SROWS/128, 3);
    hmma_gemm<<<gqkv, 256, GEMM_SMEM>>>(xh, wqh, wkh, wvh, q, k, v, DM_, INNER_, 0);
    cudaEventRecord(eQ0, 0);
    hmma_gemm<<<gqkv, 256, GEMM_SMEM>>>(xh, wqh, wkh, wvh, q, k, v, DM_, INNER_, SROWS);
    cudaEventRecord(eQ1, 0);

    // ---- side stream: attention (half-batch chunks) + state ----
    dim3 gattn(HROWS/ATT_S, H_, 1);
    cudaStreamWaitEvent(s1, eQ0, 0);
    attn_kernel<<<gattn, 256, 0, s1>>>(q, k, v, beta, ctab, stab, ah, 0, 0);
    cudaEventRecord(eA0a, s1);
    attn_kernel<<<gattn, 256, 0, s1>>>(q, k, v, beta, ctab, stab, ah, 0, HROWS);
    cudaEventRecord(eA0b, s1);
    state_part<<<H_ * STCH, 256, 0, s1>>>(k, v, beta, alpha_log, ctab, stab, stpart, 0);
    cudaStreamWaitEvent(s1, eQ1, 0);
    attn_kernel<<<gattn, 256, 0, s1>>>(q, k, v, beta, ctab, stab, ah, 1, 0);
    cudaEventRecord(eA1a, s1);
    attn_kernel<<<gattn, 256, 0, s1>>>(q, k, v, beta, ctab, stab, ah, 1, HROWS);
    cudaEventRecord(eA1b, s1);
    state_part<<<H_ * STCH, 256, 0, s1>>>(k, v, beta, alpha_log, ctab, stab, stpart, 1);
    state_comb<<<B_ * H_, 256, 0, s1>>>(stpart, alpha_log, out + (size_t)MROWS * DM_);
    cudaEventRecord(eS, s1);

    // ---- O-proj GEMMs on main stream, half-batch chunks ----
    dim3 gout(DM_/128, HROWS/128, 1);
    cudaStreamWaitEvent(0, eA0a, 0);
    hmma_gemm<<<gout, 256, GEMM_SMEM>>>(ah, woh, woh, woh, out, out, out, INNER_, DM_, 0);
    cudaStreamWaitEvent(0, eA0b, 0);
    hmma_gemm<<<gout, 256, GEMM_SMEM>>>(ah, woh, woh, woh, out, out, out, INNER_, DM_, HROWS);
    cudaStreamWaitEvent(0, eA1a, 0);
    hmma_gemm<<<gout, 256, GEMM_SMEM>>>(ah, woh, woh, woh, out, out, out, INNER_, DM_, SROWS);
    cudaStreamWaitEvent(0, eA1b, 0);
    hmma_gemm<<<gout, 256, GEMM_SMEM>>>(ah, woh, woh, woh, out, out, out, INNER_, DM_, SROWS + HROWS);

    // ---- join side stream back ----
    cudaStreamWaitEvent(0, eS, 0);
}